// round 9
// baseline (speedup 1.0000x reference)
#include <cuda_runtime.h>
#include <cuda_fp16.h>
#include <math.h>

// Problem dims
#define LAYERS 6
#define DMODEL 1024
#define NHEAD  16
#define HDIM   64
#define ROTD   16
#define IFF    4096
#define VOCAB  50304
#define BATCH  2
#define SEQ    1024
#define NTOK   (BATCH*SEQ)        // 2048
#define LN_EPS 1e-5f
#define INV_SCALE 0.125f          // 1/sqrt(64)

// ---------------- scratch (static device globals; no allocation) -------------
__device__ float  g_x[NTOK*DMODEL];
__device__ __half g_h[NTOK*DMODEL];
__device__ float  g_qkv[NTOK*3*DMODEL];
__device__ __half g_q[NTOK*DMODEL];
__device__ __half g_k[NTOK*DMODEL];
__device__ __half g_vt[NTOK*DMODEL];                      // V^T per (b,h): [HS,T]
__device__ float  g_scores[(size_t)BATCH*NHEAD*SEQ*SEQ];  // 134 MB
__device__ __half g_p[(size_t)BATCH*NHEAD*SEQ*SEQ];       // probabilities, 67 MB
__device__ __half g_mg[NTOK*DMODEL];
__device__ float  g_attd[NTOK*DMODEL];
__device__ __half g_m1[NTOK*IFF];
__device__ float  g_m2[NTOK*DMODEL];

// fp16, TRANSPOSED weight copies ([N,K] layout), built once per launch
__device__ __half g_wq[(size_t)LAYERS*DMODEL*3*DMODEL];
__device__ __half g_wd[(size_t)LAYERS*DMODEL*DMODEL];
__device__ __half g_w1[(size_t)LAYERS*DMODEL*IFF];
__device__ __half g_w2[(size_t)LAYERS*IFF*DMODEL];
__device__ __half g_wh[(size_t)DMODEL*VOCAB];

// ---------------- helpers -----------------------------------------------------
__device__ __forceinline__ float blockReduceSum(float v) {
    __shared__ float sh[8];
    int lane = threadIdx.x & 31, wid = threadIdx.x >> 5;
    #pragma unroll
    for (int o = 16; o; o >>= 1) v += __shfl_xor_sync(0xffffffffu, v, o);
    if (lane == 0) sh[wid] = v;
    __syncthreads();
    float r = 0.f;
    #pragma unroll
    for (int i = 0; i < 8; i++) r += sh[i];
    __syncthreads();
    return r;
}

__device__ __forceinline__ float blockReduceMax(float v) {
    __shared__ float sh[8];
    int lane = threadIdx.x & 31, wid = threadIdx.x >> 5;
    #pragma unroll
    for (int o = 16; o; o >>= 1) v = fmaxf(v, __shfl_xor_sync(0xffffffffu, v, o));
    if (lane == 0) sh[wid] = v;
    __syncthreads();
    float r = -1e30f;
    #pragma unroll
    for (int i = 0; i < 8; i++) r = fmaxf(r, sh[i]);
    __syncthreads();
    return r;
}

__device__ __forceinline__ float gelu_exact(float x) {
    return 0.5f * x * (1.f + erff(x * 0.70710678118654752f));
}

__device__ __forceinline__ void mma16(float* c, const unsigned* a,
                                      unsigned b0, unsigned b1) {
    asm volatile(
        "mma.sync.aligned.m16n8k16.row.col.f32.f16.f16.f32 "
        "{%0,%1,%2,%3},{%4,%5,%6,%7},{%8,%9},{%0,%1,%2,%3};"
        : "+f"(c[0]), "+f"(c[1]), "+f"(c[2]), "+f"(c[3])
        : "r"(a[0]), "r"(a[1]), "r"(a[2]), "r"(a[3]), "r"(b0), "r"(b1));
}

__device__ __forceinline__ void ldsm4(unsigned* r, unsigned saddr) {
    asm volatile(
        "ldmatrix.sync.aligned.m8n8.x4.shared.b16 {%0,%1,%2,%3}, [%4];"
        : "=r"(r[0]), "=r"(r[1]), "=r"(r[2]), "=r"(r[3]) : "r"(saddr));
}

__device__ __forceinline__ void cp16h(__half* smem, const __half* g, int sz) {
    unsigned s = (unsigned)__cvta_generic_to_shared(smem);
    asm volatile("cp.async.cg.shared.global [%0], [%1], 16, %2;\n"
                 :: "r"(s), "l"(g), "r"(sz));
}
__device__ __forceinline__ void cpcommit() {
    asm volatile("cp.async.commit_group;\n" ::);
}

// ---------------- fp16 tensor-core GEMM:  C = alpha*A.B^T (+bias) ------------
// A [M,K] half row-major, B [N,K] half row-major.  f32 accumulate.
// TBM: CTA M-tile (256 -> 8 warps, 128 -> 4 warps); BN fixed 128; BK 32 halves.
// 3-stage cp.async pipeline; warp tile 64x64.
// EPI bit0: exact GELU.  OUTH: half output.
// PVOUT=1: C base = (z>>4)*SEQ*D + (z&15)*HDIM, ldC = DMODEL (attention merge).
// CAUSAL=1: skip CTA if bn >= bm+TBM (QK^T upper triangle).
// CAUSAL=2: clamp k-range to bm+TBM (PV with causal P).
#define BN_ 128
#define ASTR 40   // halves per smem row: 80B stride == 20 words -> conflict-free
#define NS 3      // pipeline stages

template<int TBM, int EPI, int PVOUT, int OUTH, int CAUSAL>
__global__ void __launch_bounds__(TBM, 256/TBM)
gemm_h(const __half* __restrict__ A, const __half* __restrict__ B,
       const float* __restrict__ bias, void* __restrict__ Cv,
       int M, int N, int K,
       long long sA, long long sB, long long sC, float alpha)
{
    constexpr int ABYTES = TBM * ASTR * 2;
    constexpr int BBYTES = BN_ * ASTR * 2;
    extern __shared__ __half smh[];

    const int bm = blockIdx.y * TBM;
    const int bn = blockIdx.x * BN_;
    if (CAUSAL == 1 && bn >= bm + TBM) return;   // fully masked block

    const int bz = blockIdx.z;
    A += (long long)bz * sA;
    B += (long long)bz * sB;
    long long cbase, ldC;
    if (PVOUT) {
        cbase = (long long)(bz >> 4) * SEQ * DMODEL + (bz & 15) * HDIM;
        ldC = DMODEL;
    } else {
        cbase = (long long)bz * sC;
        ldC = N;
    }

    const int tid = threadIdx.x;
    const int lane = tid & 31, w = tid >> 5;
    const int wr = w >> 1, wc = w & 1;
    const int gid = lane >> 2, tig = lane & 3;
    const int m0 = wr * 64, n0 = wc * 64;

    int nk = K / 32;
    if (CAUSAL == 2) { int lim = (bm + TBM) / 32; nk = nk < lim ? nk : lim; }

    float acc[4][8][4];
    #pragma unroll
    for (int i = 0; i < 4; i++)
        #pragma unroll
        for (int j = 0; j < 8; j++)
            #pragma unroll
            for (int q = 0; q < 4; q++) acc[i][j][q] = 0.f;

    auto loadT = [&](int buf, int k0) {
        #pragma unroll
        for (int i = 0; i < 4; i++) {                 // A: TBM rows x 4 chunks
            int idx = i * TBM + tid;
            int r = idx >> 2, c8 = (idx & 3) * 8;
            cp16h(smh + buf * (TBM * ASTR) + r * ASTR + c8,
                  A + (long long)(bm + r) * K + k0 + c8, 16);
        }
        #pragma unroll
        for (int i = 0; i < BN_ * 4 / TBM; i++) {     // B: 128 rows x 4 chunks
            int idx = i * TBM + tid;
            int r = idx >> 2, c8 = (idx & 3) * 8;
            int n = bn + r;
            int ok = n < N;
            cp16h(smh + NS * (TBM * ASTR) + buf * (BN_ * ASTR) + r * ASTR + c8,
                  B + (long long)(ok ? n : 0) * K + k0 + c8, ok ? 16 : 0);
        }
    };

    // ldmatrix lane-relative byte offsets (within one buffer)
    const unsigned sbase = (unsigned)__cvta_generic_to_shared(smh);
    unsigned aoff[4], boff[4];
    {
        int rl = lane & 15, kh = (lane >> 4) * 16;
        #pragma unroll
        for (int mt = 0; mt < 4; mt++)
            aoff[mt] = (m0 + mt * 16 + rl) * (ASTR * 2) + kh;
        #pragma unroll
        for (int j = 0; j < 4; j++)
            boff[j] = (n0 + j * 16 + rl) * (ASTR * 2) + kh;
    }

    // preload first two tiles (commit one group per tile slot)
    #pragma unroll
    for (int s = 0; s < NS - 1; s++) {
        if (s < nk) loadT(s, s * 32);
        cpcommit();
    }

    for (int t = 0; t < nk; t++) {
        if (t + 1 < nk) asm volatile("cp.async.wait_group 1;" ::: "memory");
        else            asm volatile("cp.async.wait_group 0;" ::: "memory");
        __syncthreads();

        // issue next load (into buffer finished last iteration)
        if (t + NS - 1 < nk) loadT((t + NS - 1) % NS, (t + NS - 1) * 32);
        cpcommit();

        const int buf = t % NS;
        const unsigned abase = sbase + buf * ABYTES;
        const unsigned bbase = sbase + NS * ABYTES + buf * BBYTES;

        #pragma unroll
        for (int ks = 0; ks < 2; ks++) {
            unsigned af[4][4];
            #pragma unroll
            for (int mt = 0; mt < 4; mt++)
                ldsm4(af[mt], abase + aoff[mt] + ks * 32);
            #pragma unroll
            for (int j = 0; j < 4; j++) {
                unsigned bf[4];
                ldsm4(bf, bbase + boff[j] + ks * 32);
                #pragma unroll
                for (int mt = 0; mt < 4; mt++) {
                    mma16(acc[mt][2*j],   af[mt], bf[0], bf[2]);
                    mma16(acc[mt][2*j+1], af[mt], bf[1], bf[3]);
                }
            }
        }
    }

    // ---- epilogue ----
    #pragma unroll
    for (int mt = 0; mt < 4; mt++) {
        const int r0 = bm + m0 + mt * 16 + gid;
        #pragma unroll
        for (int nt = 0; nt < 8; nt++) {
            int c = bn + n0 + nt * 8 + 2 * tig;
            if (c < N) {
                float* a4 = acc[mt][nt];
                float v0 = a4[0] * alpha, v1 = a4[1] * alpha;
                float v2 = a4[2] * alpha, v3 = a4[3] * alpha;
                if (bias) {
                    float bv0 = bias[c], bv1 = bias[c + 1];
                    v0 += bv0; v1 += bv1; v2 += bv0; v3 += bv1;
                }
                if (EPI & 1) {
                    v0 = gelu_exact(v0); v1 = gelu_exact(v1);
                    v2 = gelu_exact(v2); v3 = gelu_exact(v3);
                }
                if (OUTH) {
                    __half* Ch = (__half*)Cv + cbase;
                    *(__half2*)(Ch + (long long)r0 * ldC + c) =
                        __floats2half2_rn(v0, v1);
                    *(__half2*)(Ch + (long long)(r0 + 8) * ldC + c) =
                        __floats2half2_rn(v2, v3);
                } else {
                    float* Cf = (float*)Cv + cbase;
                    *(float2*)(Cf + (long long)r0 * ldC + c) = make_float2(v0, v1);
                    *(float2*)(Cf + (long long)(r0 + 8) * ldC + c) = make_float2(v2, v3);
                }
            }
        }
    }
}

// ---------------- weight transpose f32[R][C] -> half[C][R] -------------------
__global__ void wtr_k(const float* __restrict__ in, __half* __restrict__ out,
                      int R, int C)
{
    __shared__ float t[32][33];
    in  += (size_t)blockIdx.z * R * C;
    out += (size_t)blockIdx.z * R * C;
    int r0 = blockIdx.y * 32, c0 = blockIdx.x * 32;
    #pragma unroll
    for (int i = threadIdx.y; i < 32; i += 8)
        t[i][threadIdx.x] = in[(size_t)(r0 + i) * C + c0 + threadIdx.x];
    __syncthreads();
    #pragma unroll
    for (int i = threadIdx.y; i < 32; i += 8)
        out[(size_t)(c0 + i) * R + r0 + threadIdx.x] =
            __float2half_rn(t[threadIdx.x][i]);
}

// V^T from f32 qkv: vt[(bh*HS + d)*T + t] = half(V[b,t,h,d])
__global__ void vt_k(const float* __restrict__ qkv, __half* __restrict__ vt)
{
    __shared__ float tile[32][33];
    int bh = blockIdx.z;
    int b = bh >> 4, h = bh & 15;
    int t0 = blockIdx.x * 32, d0 = blockIdx.y * 32;
    #pragma unroll
    for (int i = threadIdx.y; i < 32; i += 8) {
        int t = t0 + i;
        tile[i][threadIdx.x] = qkv[((size_t)(b * SEQ + t)) * (3 * DMODEL)
                                   + h * 3 * HDIM + 2 * HDIM + d0 + threadIdx.x];
    }
    __syncthreads();
    #pragma unroll
    for (int i = threadIdx.y; i < 32; i += 8) {
        int d = d0 + i;
        vt[((size_t)bh * HDIM + d) * SEQ + t0 + threadIdx.x] =
            __float2half_rn(tile[threadIdx.x][i]);
    }
}

// ---------------- elementwise kernels ----------------------------------------
__global__ void embed_k(const int* __restrict__ ids,
                        const float* __restrict__ ew, float* __restrict__ x)
{
    int idx = blockIdx.x * blockDim.x + threadIdx.x;
    if (idx >= NTOK * DMODEL) return;
    int row = idx / DMODEL, d = idx % DMODEL;
    x[idx] = ew[(long long)ids[row] * DMODEL + d];
}

// LayerNorm f32 -> half
__global__ void ln_k(const float* __restrict__ x, const float* __restrict__ s,
                     const float* __restrict__ b, __half* __restrict__ out)
{
    int row = blockIdx.x;
    const float4* xr = (const float4*)(x + (long long)row * DMODEL);
    float4 v = xr[threadIdx.x];
    float sum = v.x + v.y + v.z + v.w;
    float mean = blockReduceSum(sum) * (1.f / DMODEL);
    float dx = v.x - mean, dy = v.y - mean, dz = v.z - mean, dw = v.w - mean;
    float var = blockReduceSum(dx*dx + dy*dy + dz*dz + dw*dw) * (1.f / DMODEL);
    float r = rsqrtf(var + LN_EPS);
    float4 s4 = ((const float4*)s)[threadIdx.x];
    float4 b4 = ((const float4*)b)[threadIdx.x];
    __half2* orow = (__half2*)(out + (long long)row * DMODEL);
    orow[2*threadIdx.x]   = __floats2half2_rn(dx * r * s4.x + b4.x,
                                              dy * r * s4.y + b4.y);
    orow[2*threadIdx.x+1] = __floats2half2_rn(dz * r * s4.z + b4.z,
                                              dw * r * s4.w + b4.w);
}

// f32 qkv -> rope q,k -> half Q,K [B,H,T,HS]
__global__ void rope_split_k(const float* __restrict__ qkv,
                             __half* __restrict__ Q, __half* __restrict__ K)
{
    int idx = blockIdx.x * blockDim.x + threadIdx.x;
    if (idx >= NTOK * DMODEL) return;
    int d = idx & (HDIM - 1);
    int t = (idx >> 6) & (SEQ - 1);
    int h = (idx >> 16) & (NHEAD - 1);
    int b = idx >> 20;
    long long base = ((long long)(b * SEQ + t)) * (3 * DMODEL) + h * (3 * HDIM);
    float qv = qkv[base + d];
    float kv = qkv[base + HDIM + d];
    if (d < ROTD) {
        int fi = d & 7;
        float inv = expf(-(float)(2 * fi) / ROTD * logf(10000.0f));
        float ang = (float)t * inv;
        float c = cosf(ang), s = sinf(ang);
        int partner = (d < 8) ? d + 8 : d - 8;
        float qp = qkv[base + partner];
        float kp = qkv[base + HDIM + partner];
        float rq = (d < 8) ? -qp : qp;
        float rk = (d < 8) ? -kp : kp;
        qv = qv * c + rq * s;
        kv = kv * c + rk * s;
    }
    Q[idx] = __float2half_rn(qv); K[idx] = __float2half_rn(kv);
}

// causal softmax: f32 scores -> half probabilities.
// Writes zeros only up to the 128-aligned boundary (what causal PV reads).
__global__ void softmax_k(const float* __restrict__ sc, __half* __restrict__ p)
{
    __shared__ float ebuf[SEQ];
    long long r = blockIdx.x;
    int i = (int)(r & (SEQ - 1));
    const float* row = sc + r * SEQ;
    __half* prow = p + r * SEQ;
    int tid = threadIdx.x;
    float mx = -1e30f;
    for (int j = tid; j <= i; j += 256) mx = fmaxf(mx, row[j]);
    mx = blockReduceMax(mx);
    float sum = 0.f;
    for (int j = tid; j <= i; j += 256) {
        float e = expf(row[j] - mx);
        ebuf[j] = e;
        sum += e;
    }
    sum = blockReduceSum(sum);
    __syncthreads();
    float inv = 1.f / sum;
    int lim = ((i >> 7) + 1) << 7;           // PV reads keys < lim
    for (int j = tid; j < lim; j += 256)
        prow[j] = (j <= i) ? __float2half_rn(ebuf[j] * inv)
                           : __float2half_rn(0.f);
}

// x += a + c
__global__ void add3_k(float* __restrict__ x, const float* __restrict__ a,
                       const float* __restrict__ c)
{
    int idx = blockIdx.x * blockDim.x + threadIdx.x;
    if (idx >= NTOK * DMODEL / 4) return;
    float4 xv = ((const float4*)x)[idx];
    float4 av = ((const float4*)a)[idx];
    float4 cv = ((const float4*)c)[idx];
    xv.x += av.x + cv.x; xv.y += av.y + cv.y;
    xv.z += av.z + cv.z; xv.w += av.w + cv.w;
    ((float4*)x)[idx] = xv;
}

#define S256 (NS*(256*ASTR*2 + BN_*ASTR*2))   // 92160
#define S128 (NS*(128*ASTR*2 + BN_*ASTR*2))   // 61440

// ---------------- driver ------------------------------------------------------
extern "C" void kernel_launch(void* const* d_in, const int* in_sizes, int n_in,
                              void* d_out, int out_size)
{
    const int*   ids     = (const int*)  d_in[0];
    const float* embed_w = (const float*)d_in[1];
    const float* ln1_s   = (const float*)d_in[2];
    const float* ln1_b   = (const float*)d_in[3];
    const float* ln2_s   = (const float*)d_in[4];
    const float* ln2_b   = (const float*)d_in[5];
    const float* qkv_w   = (const float*)d_in[6];
    const float* qkv_b   = (const float*)d_in[7];
    const float* dense_w = (const float*)d_in[8];
    const float* dense_b = (const float*)d_in[9];
    const float* fc1_w   = (const float*)d_in[10];
    const float* fc1_b   = (const float*)d_in[11];
    const float* fc2_w   = (const float*)d_in[12];
    const float* fc2_b   = (const float*)d_in[13];
    const float* fln_s   = (const float*)d_in[14];
    const float* fln_b   = (const float*)d_in[15];
    const float* head_w  = (const float*)d_in[16];
    float* out = (float*)d_out;

    cudaFuncSetAttribute(gemm_h<256,0,0,0,0>, cudaFuncAttributeMaxDynamicSharedMemorySize, S256);
    cudaFuncSetAttribute(gemm_h<256,0,0,0,1>, cudaFuncAttributeMaxDynamicSharedMemorySize, S256);
    cudaFuncSetAttribute(gemm_h<256,1,0,1,0>, cudaFuncAttributeMaxDynamicSharedMemorySize, S256);
    cudaFuncSetAttribute(gemm_h<128,0,1,1,2>, cudaFuncAttributeMaxDynamicSharedMemorySize, S128);
    cudaFuncSetAttribute(gemm_h<128,0,0,0,0>, cudaFuncAttributeMaxDynamicSharedMemorySize, S128);

    float *x, *qkv, *sc, *ad, *m2;
    __half *h, *Q, *K, *Vt, *p, *mg, *m1;
    __half *wq, *wd, *w1, *w2, *wh;
    cudaGetSymbolAddress((void**)&x,   g_x);
    cudaGetSymbolAddress((void**)&h,   g_h);
    cudaGetSymbolAddress((void**)&qkv, g_qkv);
    cudaGetSymbolAddress((void**)&Q,   g_q);
    cudaGetSymbolAddress((void**)&K,   g_k);
    cudaGetSymbolAddress((void**)&Vt,  g_vt);
    cudaGetSymbolAddress((void**)&sc,  g_scores);
    cudaGetSymbolAddress((void**)&p,   g_p);
    cudaGetSymbolAddress((void**)&mg,  g_mg);
    cudaGetSymbolAddress((void**)&ad,  g_attd);
    cudaGetSymbolAddress((void**)&m1,  g_m1);
    cudaGetSymbolAddress((void**)&m2,  g_m2);
    cudaGetSymbolAddress((void**)&wq,  g_wq);
    cudaGetSymbolAddress((void**)&wd,  g_wd);
    cudaGetSymbolAddress((void**)&w1,  g_w1);
    cudaGetSymbolAddress((void**)&w2,  g_w2);
    cudaGetSymbolAddress((void**)&wh,  g_wh);

    const int ELTS = NTOK * DMODEL;
    dim3 tb(32, 8);

    // ---- one-shot weight transpose + fp16 conversion ([K,N] -> [N,K]) ----
    wtr_k<<<dim3(3*DMODEL/32, DMODEL/32, LAYERS), tb>>>(qkv_w,  wq, DMODEL, 3*DMODEL);
    wtr_k<<<dim3(DMODEL/32,  DMODEL/32, LAYERS), tb>>>(dense_w, wd, DMODEL, DMODEL);
    wtr_k<<<dim3(IFF/32,     DMODEL/32, LAYERS), tb>>>(fc1_w,   w1, DMODEL, IFF);
    wtr_k<<<dim3(DMODEL/32,  IFF/32,    LAYERS), tb>>>(fc2_w,   w2, IFF, DMODEL);
    wtr_k<<<dim3(VOCAB/32,   DMODEL/32, 1),      tb>>>(head_w,  wh, DMODEL, VOCAB);

    embed_k<<<(ELTS + 255) / 256, 256>>>(ids, embed_w, x);

    for (int l = 0; l < LAYERS; l++) {
        // ---- attention branch ----
        ln_k<<<NTOK, 256>>>(x, ln1_s + l * DMODEL, ln1_b + l * DMODEL, h);
        gemm_h<256,0,0,0,0><<<dim3(3 * DMODEL / BN_, NTOK / 256, 1), 256, S256>>>(
            h, wq + (size_t)l * DMODEL * 3 * DMODEL,
            qkv_b + (size_t)l * 3 * DMODEL, qkv,
            NTOK, 3 * DMODEL, DMODEL, 0, 0, 0, 1.f);
        rope_split_k<<<(ELTS + 255) / 256, 256>>>(qkv, Q, K);
        vt_k<<<dim3(SEQ/32, HDIM/32, BATCH*NHEAD), tb>>>(qkv, Vt);
        // scores = Q K^T / sqrt(HS), causal blocks only
        gemm_h<256,0,0,0,1><<<dim3(SEQ / BN_, SEQ / 256, BATCH * NHEAD), 256, S256>>>(
            Q, K, nullptr, sc,
            SEQ, SEQ, HDIM,
            (long long)SEQ * HDIM, (long long)SEQ * HDIM,
            (long long)SEQ * SEQ, INV_SCALE);
        softmax_k<<<BATCH * NHEAD * SEQ, 256>>>(sc, p);
        // O = P V (B = V^T [HS,T]); causal k-clamp; merged [B,T,D] half out
        gemm_h<128,0,1,1,2><<<dim3(1, SEQ / 128, BATCH * NHEAD), 128, S128>>>(
            p, Vt, nullptr, mg,
            SEQ, HDIM, SEQ,
            (long long)SEQ * SEQ, (long long)HDIM * SEQ, 0, 1.f);
        gemm_h<128,0,0,0,0><<<dim3(DMODEL / BN_, NTOK / 128, 1), 128, S128>>>(
            mg, wd + (size_t)l * DMODEL * DMODEL,
            dense_b + (size_t)l * DMODEL, ad,
            NTOK, DMODEL, DMODEL, 0, 0, 0, 1.f);
        // ---- MLP branch (on original x) ----
        ln_k<<<NTOK, 256>>>(x, ln2_s + l * DMODEL, ln2_b + l * DMODEL, h);
        gemm_h<256,1,0,1,0><<<dim3(IFF / BN_, NTOK / 256, 1), 256, S256>>>(
            h, w1 + (size_t)l * DMODEL * IFF,
            fc1_b + (size_t)l * IFF, m1,
            NTOK, IFF, DMODEL, 0, 0, 0, 1.f);
        gemm_h<128,0,0,0,0><<<dim3(DMODEL / BN_, NTOK / 128, 1), 128, S128>>>(
            m1, w2 + (size_t)l * IFF * DMODEL,
            fc2_b + (size_t)l * DMODEL, m2,
            NTOK, DMODEL, IFF, 0, 0, 0, 1.f);
        // ---- residual: x = x + attn_out + mlp_out ----
        add3_k<<<(ELTS / 4 + 255) / 256, 256>>>(x, ad, m2);
    }

    // final LN + head
    ln_k<<<NTOK, 256>>>(x, fln_s, fln_b, h);
    gemm_h<256,0,0,0,0><<<dim3(VOCAB / BN_, NTOK / 256, 1), 256, S256>>>(
        h, wh, nullptr, out,
        NTOK, VOCAB, DMODEL, 0, 0, 0, 1.f);
}

// round 11
// speedup vs baseline: 1.4615x; 1.4615x over previous
#include <cuda_runtime.h>
#include <cuda_fp16.h>
#include <math.h>

// Problem dims
#define LAYERS 6
#define DMODEL 1024
#define NHEAD  16
#define HDIM   64
#define ROTD   16
#define IFF    4096
#define VOCAB  50304
#define BATCH  2
#define SEQ    1024
#define NTOK   (BATCH*SEQ)        // 2048
#define LN_EPS 1e-5f
#define INV_SCALE 0.125f          // 1/sqrt(64)

// ---------------- scratch (static device globals; no allocation) -------------
__device__ float  g_x[NTOK*DMODEL];
__device__ __half g_h[NTOK*DMODEL];
__device__ float  g_qkv[NTOK*3*DMODEL];
__device__ __half g_q[NTOK*DMODEL];
__device__ __half g_k[NTOK*DMODEL];
__device__ __half g_vt[NTOK*DMODEL];                      // V^T per (b,h): [HS,T]
__device__ float  g_scores[(size_t)BATCH*NHEAD*SEQ*SEQ];  // 134 MB
__device__ __half g_p[(size_t)BATCH*NHEAD*SEQ*SEQ];       // probabilities, 67 MB
__device__ __half g_mg[NTOK*DMODEL];
__device__ float  g_attd[NTOK*DMODEL];
__device__ __half g_m1[NTOK*IFF];
__device__ float  g_m2[NTOK*DMODEL];

// fp16, TRANSPOSED weight copies ([N,K] layout), built once per launch
__device__ __half g_wq[(size_t)LAYERS*DMODEL*3*DMODEL];
__device__ __half g_wd[(size_t)LAYERS*DMODEL*DMODEL];
__device__ __half g_w1[(size_t)LAYERS*DMODEL*IFF];
__device__ __half g_w2[(size_t)LAYERS*IFF*DMODEL];
__device__ __half g_wh[(size_t)DMODEL*VOCAB];

// ---------------- helpers -----------------------------------------------------
__device__ __forceinline__ float blockReduceSum(float v) {
    __shared__ float sh[8];
    int lane = threadIdx.x & 31, wid = threadIdx.x >> 5;
    #pragma unroll
    for (int o = 16; o; o >>= 1) v += __shfl_xor_sync(0xffffffffu, v, o);
    if (lane == 0) sh[wid] = v;
    __syncthreads();
    float r = 0.f;
    #pragma unroll
    for (int i = 0; i < 8; i++) r += sh[i];
    __syncthreads();
    return r;
}

__device__ __forceinline__ float blockReduceMax(float v) {
    __shared__ float sh[8];
    int lane = threadIdx.x & 31, wid = threadIdx.x >> 5;
    #pragma unroll
    for (int o = 16; o; o >>= 1) v = fmaxf(v, __shfl_xor_sync(0xffffffffu, v, o));
    if (lane == 0) sh[wid] = v;
    __syncthreads();
    float r = -1e30f;
    #pragma unroll
    for (int i = 0; i < 8; i++) r = fmaxf(r, sh[i]);
    __syncthreads();
    return r;
}

__device__ __forceinline__ float gelu_exact(float x) {
    return 0.5f * x * (1.f + erff(x * 0.70710678118654752f));
}

__device__ __forceinline__ void mma16(float* c, const unsigned* a,
                                      unsigned b0, unsigned b1) {
    asm volatile(
        "mma.sync.aligned.m16n8k16.row.col.f32.f16.f16.f32 "
        "{%0,%1,%2,%3},{%4,%5,%6,%7},{%8,%9},{%0,%1,%2,%3};"
        : "+f"(c[0]), "+f"(c[1]), "+f"(c[2]), "+f"(c[3])
        : "r"(a[0]), "r"(a[1]), "r"(a[2]), "r"(a[3]), "r"(b0), "r"(b1));
}

__device__ __forceinline__ void ldsm4(unsigned* r, unsigned saddr) {
    asm volatile(
        "ldmatrix.sync.aligned.m8n8.x4.shared.b16 {%0,%1,%2,%3}, [%4];"
        : "=r"(r[0]), "=r"(r[1]), "=r"(r[2]), "=r"(r[3]) : "r"(saddr));
}

__device__ __forceinline__ void cp16h(__half* smem, const __half* g, int sz) {
    unsigned s = (unsigned)__cvta_generic_to_shared(smem);
    asm volatile("cp.async.cg.shared.global [%0], [%1], 16, %2;\n"
                 :: "r"(s), "l"(g), "r"(sz));
}
__device__ __forceinline__ void cpcommit() {
    asm volatile("cp.async.commit_group;\n" ::);
}
__device__ __forceinline__ void cpwait0() {
    asm volatile("cp.async.wait_group 0;\n" ::: "memory");
}

// ---------------- fp16 tensor-core GEMM:  C = alpha*A.B^T (+bias) ------------
// A [M,K] half row-major, B [N,K] half row-major.  f32 accumulate.
// TBM: CTA M-tile (256 -> 8 warps, 128 -> 4 warps); BN fixed 128; BK 32 halves.
// Warp tile 64x64.  EPI bit0: exact GELU.  OUTH: write half, else float.
// PVOUT=1: C base = (z>>4)*SEQ*D + (z&15)*HDIM, ldC = DMODEL (attention merge).
// CAUSAL=1: skip CTA if bn >= bm+TBM (QK^T upper triangle).
// CAUSAL=2: clamp k-range to bm+TBM (PV with causal P).
#define BN_ 128
#define ASTR 40   // halves per smem row: 80B stride == 20 words -> conflict-free

template<int TBM, int EPI, int PVOUT, int OUTH, int CAUSAL>
__global__ void __launch_bounds__(TBM, 256/TBM)
gemm_h(const __half* __restrict__ A, const __half* __restrict__ B,
       const float* __restrict__ bias, void* __restrict__ Cv,
       int M, int N, int K,
       long long sA, long long sB, long long sC, float alpha)
{
    constexpr int ABYTES = TBM * ASTR * 2;
    constexpr int BBYTES = BN_ * ASTR * 2;
    extern __shared__ __half smh[];

    const int bm = blockIdx.y * TBM;
    const int bn = blockIdx.x * BN_;
    if (CAUSAL == 1 && bn >= bm + TBM) return;   // fully masked score block

    const int bz = blockIdx.z;
    A += (long long)bz * sA;
    B += (long long)bz * sB;
    long long cbase, ldC;
    if (PVOUT) {
        cbase = (long long)(bz >> 4) * SEQ * DMODEL + (bz & 15) * HDIM;
        ldC = DMODEL;
    } else {
        cbase = (long long)bz * sC;
        ldC = N;
    }

    const int tid = threadIdx.x;
    const int lane = tid & 31, w = tid >> 5;
    const int wr = w >> 1, wc = w & 1;
    const int gid = lane >> 2, tig = lane & 3;
    const int m0 = wr * 64, n0 = wc * 64;

    int nk = K / 32;
    if (CAUSAL == 2) { int lim = (bm + TBM) / 32; nk = nk < lim ? nk : lim; }

    float acc[4][8][4];
    #pragma unroll
    for (int i = 0; i < 4; i++)
        #pragma unroll
        for (int j = 0; j < 8; j++)
            #pragma unroll
            for (int q = 0; q < 4; q++) acc[i][j][q] = 0.f;

    auto loadT = [&](int buf, int k0) {
        #pragma unroll
        for (int i = 0; i < 4; i++) {                 // A: TBM rows x 4 chunks
            int idx = i * TBM + tid;
            int r = idx >> 2, c8 = (idx & 3) * 8;
            cp16h(smh + buf * (TBM * ASTR) + r * ASTR + c8,
                  A + (long long)(bm + r) * K + k0 + c8, 16);
        }
        #pragma unroll
        for (int i = 0; i < BN_ * 4 / TBM; i++) {     // B: 128 rows x 4 chunks
            int idx = i * TBM + tid;
            int r = idx >> 2, c8 = (idx & 3) * 8;
            int n = bn + r;
            int ok = n < N;
            cp16h(smh + 2 * (TBM * ASTR) + buf * (BN_ * ASTR) + r * ASTR + c8,
                  B + (long long)(ok ? n : 0) * K + k0 + c8, ok ? 16 : 0);
        }
        cpcommit();
    };

    // ldmatrix lane-relative byte offsets
    const unsigned sbase = (unsigned)__cvta_generic_to_shared(smh);
    unsigned aoff[4], boff[4];
    {
        int rl = lane & 15, kh = (lane >> 4) * 16;
        #pragma unroll
        for (int mt = 0; mt < 4; mt++)
            aoff[mt] = (m0 + mt * 16 + rl) * (ASTR * 2) + kh;
        #pragma unroll
        for (int j = 0; j < 4; j++)
            boff[j] = (unsigned)(2 * ABYTES) + (n0 + j * 16 + rl) * (ASTR * 2) + kh;
    }

    loadT(0, 0);
    for (int t = 0; t < nk; t++) {
        cpwait0();
        __syncthreads();
        if (t + 1 < nk) loadT((t + 1) & 1, (t + 1) * 32);

        const unsigned abase = sbase + (t & 1) * ABYTES;
        const unsigned bbase = sbase + (t & 1) * BBYTES;

        #pragma unroll
        for (int ks = 0; ks < 2; ks++) {
            unsigned af[4][4];
            #pragma unroll
            for (int mt = 0; mt < 4; mt++)
                ldsm4(af[mt], abase + aoff[mt] + ks * 32);
            #pragma unroll
            for (int j = 0; j < 4; j++) {
                unsigned bf[4];
                ldsm4(bf, bbase + boff[j] + ks * 32);
                #pragma unroll
                for (int mt = 0; mt < 4; mt++) {
                    mma16(acc[mt][2*j],   af[mt], bf[0], bf[2]);
                    mma16(acc[mt][2*j+1], af[mt], bf[1], bf[3]);
                }
            }
        }
        __syncthreads();
    }

    // ---- epilogue ----
    #pragma unroll
    for (int mt = 0; mt < 4; mt++) {
        const int r0 = bm + m0 + mt * 16 + gid;
        #pragma unroll
        for (int nt = 0; nt < 8; nt++) {
            int c = bn + n0 + nt * 8 + 2 * tig;
            if (c < N) {
                float* a4 = acc[mt][nt];
                float v0 = a4[0] * alpha, v1 = a4[1] * alpha;
                float v2 = a4[2] * alpha, v3 = a4[3] * alpha;
                if (bias) {
                    float bv0 = bias[c], bv1 = bias[c + 1];
                    v0 += bv0; v1 += bv1; v2 += bv0; v3 += bv1;
                }
                if (EPI & 1) {
                    v0 = gelu_exact(v0); v1 = gelu_exact(v1);
                    v2 = gelu_exact(v2); v3 = gelu_exact(v3);
                }
                if (OUTH) {
                    __half* Ch = (__half*)Cv + cbase;
                    *(__half2*)(Ch + (long long)r0 * ldC + c) =
                        __floats2half2_rn(v0, v1);
                    *(__half2*)(Ch + (long long)(r0 + 8) * ldC + c) =
                        __floats2half2_rn(v2, v3);
                } else {
                    float* Cf = (float*)Cv + cbase;
                    *(float2*)(Cf + (long long)r0 * ldC + c) = make_float2(v0, v1);
                    *(float2*)(Cf + (long long)(r0 + 8) * ldC + c) = make_float2(v2, v3);
                }
            }
        }
    }
}

// ---------------- weight transpose f32[R][C] -> half[C][R] -------------------
__global__ void wtr_k(const float* __restrict__ in, __half* __restrict__ out,
                      int R, int C)
{
    __shared__ float t[32][33];
    in  += (size_t)blockIdx.z * R * C;
    out += (size_t)blockIdx.z * R * C;
    int r0 = blockIdx.y * 32, c0 = blockIdx.x * 32;
    #pragma unroll
    for (int i = threadIdx.y; i < 32; i += 8)
        t[i][threadIdx.x] = in[(size_t)(r0 + i) * C + c0 + threadIdx.x];
    __syncthreads();
    #pragma unroll
    for (int i = threadIdx.y; i < 32; i += 8)
        out[(size_t)(c0 + i) * R + r0 + threadIdx.x] =
            __float2half_rn(t[threadIdx.x][i]);
}

// V^T from f32 qkv: vt[(bh*HS + d)*T + t] = half(V[b,t,h,d])
__global__ void vt_k(const float* __restrict__ qkv, __half* __restrict__ vt)
{
    __shared__ float tile[32][33];
    int bh = blockIdx.z;
    int b = bh >> 4, h = bh & 15;
    int t0 = blockIdx.x * 32, d0 = blockIdx.y * 32;
    #pragma unroll
    for (int i = threadIdx.y; i < 32; i += 8) {
        int t = t0 + i;
        tile[i][threadIdx.x] = qkv[((size_t)(b * SEQ + t)) * (3 * DMODEL)
                                   + h * 3 * HDIM + 2 * HDIM + d0 + threadIdx.x];
    }
    __syncthreads();
    #pragma unroll
    for (int i = threadIdx.y; i < 32; i += 8) {
        int d = d0 + i;
        vt[((size_t)bh * HDIM + d) * SEQ + t0 + threadIdx.x] =
            __float2half_rn(tile[threadIdx.x][i]);
    }
}

// ---------------- elementwise kernels ----------------------------------------
__global__ void embed_k(const int* __restrict__ ids,
                        const float* __restrict__ ew, float* __restrict__ x)
{
    int idx = blockIdx.x * blockDim.x + threadIdx.x;
    if (idx >= NTOK * DMODEL) return;
    int row = idx / DMODEL, d = idx % DMODEL;
    x[idx] = ew[(long long)ids[row] * DMODEL + d];
}

// LayerNorm f32 -> half
__global__ void ln_k(const float* __restrict__ x, const float* __restrict__ s,
                     const float* __restrict__ b, __half* __restrict__ out)
{
    int row = blockIdx.x;
    const float4* xr = (const float4*)(x + (long long)row * DMODEL);
    float4 v = xr[threadIdx.x];
    float sum = v.x + v.y + v.z + v.w;
    float mean = blockReduceSum(sum) * (1.f / DMODEL);
    float dx = v.x - mean, dy = v.y - mean, dz = v.z - mean, dw = v.w - mean;
    float var = blockReduceSum(dx*dx + dy*dy + dz*dz + dw*dw) * (1.f / DMODEL);
    float r = rsqrtf(var + LN_EPS);
    float4 s4 = ((const float4*)s)[threadIdx.x];
    float4 b4 = ((const float4*)b)[threadIdx.x];
    __half2* orow = (__half2*)(out + (long long)row * DMODEL);
    orow[2*threadIdx.x]   = __floats2half2_rn(dx * r * s4.x + b4.x,
                                              dy * r * s4.y + b4.y);
    orow[2*threadIdx.x+1] = __floats2half2_rn(dz * r * s4.z + b4.z,
                                              dw * r * s4.w + b4.w);
}

// f32 qkv -> rope q,k -> half Q,K [B,H,T,HS]
__global__ void rope_split_k(const float* __restrict__ qkv,
                             __half* __restrict__ Q, __half* __restrict__ K)
{
    int idx = blockIdx.x * blockDim.x + threadIdx.x;
    if (idx >= NTOK * DMODEL) return;
    int d = idx & (HDIM - 1);
    int t = (idx >> 6) & (SEQ - 1);
    int h = (idx >> 16) & (NHEAD - 1);
    int b = idx >> 20;
    long long base = ((long long)(b * SEQ + t)) * (3 * DMODEL) + h * (3 * HDIM);
    float qv = qkv[base + d];
    float kv = qkv[base + HDIM + d];
    if (d < ROTD) {
        int fi = d & 7;
        float inv = expf(-(float)(2 * fi) / ROTD * logf(10000.0f));
        float ang = (float)t * inv;
        float c = cosf(ang), s = sinf(ang);
        int partner = (d < 8) ? d + 8 : d - 8;
        float qp = qkv[base + partner];
        float kp = qkv[base + HDIM + partner];
        float rq = (d < 8) ? -qp : qp;
        float rk = (d < 8) ? -kp : kp;
        qv = qv * c + rq * s;
        kv = kv * c + rk * s;
    }
    Q[idx] = __float2half_rn(qv); K[idx] = __float2half_rn(kv);
}

// causal softmax: f32 scores -> half probabilities.
// exp cached in smem; writes only up to the 128-aligned causal boundary.
__global__ void softmax_k(const float* __restrict__ sc, __half* __restrict__ p)
{
    __shared__ float ebuf[SEQ];
    long long r = blockIdx.x;
    int i = (int)(r & (SEQ - 1));
    const float* row = sc + r * SEQ;
    __half* prow = p + r * SEQ;
    int tid = threadIdx.x;
    float mx = -1e30f;
    for (int j = tid; j <= i; j += 256) mx = fmaxf(mx, row[j]);
    mx = blockReduceMax(mx);
    float sum = 0.f;
    for (int j = tid; j <= i; j += 256) {
        float e = expf(row[j] - mx);
        ebuf[j] = e;
        sum += e;
    }
    sum = blockReduceSum(sum);
    __syncthreads();
    float inv = 1.f / sum;
    int lim = ((i >> 7) + 1) << 7;           // causal PV reads keys < lim only
    for (int j = tid; j < lim; j += 256)
        prow[j] = (j <= i) ? __float2half_rn(ebuf[j] * inv)
                           : __float2half_rn(0.f);
}

// x += a + c
__global__ void add3_k(float* __restrict__ x, const float* __restrict__ a,
                       const float* __restrict__ c)
{
    int idx = blockIdx.x * blockDim.x + threadIdx.x;
    if (idx >= NTOK * DMODEL / 4) return;
    float4 xv = ((const float4*)x)[idx];
    float4 av = ((const float4*)a)[idx];
    float4 cv = ((const float4*)c)[idx];
    xv.x += av.x + cv.x; xv.y += av.y + cv.y;
    xv.z += av.z + cv.z; xv.w += av.w + cv.w;
    ((float4*)x)[idx] = xv;
}

#define S256 (2*(256*ASTR*2 + BN_*ASTR*2))   // 61440
#define S128 (2*(128*ASTR*2 + BN_*ASTR*2))   // 40960

// ---------------- driver ------------------------------------------------------
extern "C" void kernel_launch(void* const* d_in, const int* in_sizes, int n_in,
                              void* d_out, int out_size)
{
    const int*   ids     = (const int*)  d_in[0];
    const float* embed_w = (const float*)d_in[1];
    const float* ln1_s   = (const float*)d_in[2];
    const float* ln1_b   = (const float*)d_in[3];
    const float* ln2_s   = (const float*)d_in[4];
    const float* ln2_b   = (const float*)d_in[5];
    const float* qkv_w   = (const float*)d_in[6];
    const float* qkv_b   = (const float*)d_in[7];
    const float* dense_w = (const float*)d_in[8];
    const float* dense_b = (const float*)d_in[9];
    const float* fc1_w   = (const float*)d_in[10];
    const float* fc1_b   = (const float*)d_in[11];
    const float* fc2_w   = (const float*)d_in[12];
    const float* fc2_b   = (const float*)d_in[13];
    const float* fln_s   = (const float*)d_in[14];
    const float* fln_b   = (const float*)d_in[15];
    const float* head_w  = (const float*)d_in[16];
    float* out = (float*)d_out;

    cudaFuncSetAttribute(gemm_h<256,0,0,0,0>, cudaFuncAttributeMaxDynamicSharedMemorySize, S256);
    cudaFuncSetAttribute(gemm_h<256,0,0,0,1>, cudaFuncAttributeMaxDynamicSharedMemorySize, S256);
    cudaFuncSetAttribute(gemm_h<256,1,0,1,0>, cudaFuncAttributeMaxDynamicSharedMemorySize, S256);
    cudaFuncSetAttribute(gemm_h<128,0,1,1,2>, cudaFuncAttributeMaxDynamicSharedMemorySize, S128);
    cudaFuncSetAttribute(gemm_h<128,0,0,0,0>, cudaFuncAttributeMaxDynamicSharedMemorySize, S128);

    float *x, *qkv, *sc, *ad, *m2;
    __half *h, *Q, *K, *Vt, *p, *mg, *m1;
    __half *wq, *wd, *w1, *w2, *wh;
    cudaGetSymbolAddress((void**)&x,   g_x);
    cudaGetSymbolAddress((void**)&h,   g_h);
    cudaGetSymbolAddress((void**)&qkv, g_qkv);
    cudaGetSymbolAddress((void**)&Q,   g_q);
    cudaGetSymbolAddress((void**)&K,   g_k);
    cudaGetSymbolAddress((void**)&Vt,  g_vt);
    cudaGetSymbolAddress((void**)&sc,  g_scores);
    cudaGetSymbolAddress((void**)&p,   g_p);
    cudaGetSymbolAddress((void**)&mg,  g_mg);
    cudaGetSymbolAddress((void**)&ad,  g_attd);
    cudaGetSymbolAddress((void**)&m1,  g_m1);
    cudaGetSymbolAddress((void**)&m2,  g_m2);
    cudaGetSymbolAddress((void**)&wq,  g_wq);
    cudaGetSymbolAddress((void**)&wd,  g_wd);
    cudaGetSymbolAddress((void**)&w1,  g_w1);
    cudaGetSymbolAddress((void**)&w2,  g_w2);
    cudaGetSymbolAddress((void**)&wh,  g_wh);

    const int ELTS = NTOK * DMODEL;
    dim3 tb(32, 8);

    // ---- one-shot weight transpose + fp16 conversion ([K,N] -> [N,K]) ----
    wtr_k<<<dim3(3*DMODEL/32, DMODEL/32, LAYERS), tb>>>(qkv_w,  wq, DMODEL, 3*DMODEL);
    wtr_k<<<dim3(DMODEL/32,  DMODEL/32, LAYERS), tb>>>(dense_w, wd, DMODEL, DMODEL);
    wtr_k<<<dim3(IFF/32,     DMODEL/32, LAYERS), tb>>>(fc1_w,   w1, DMODEL, IFF);
    wtr_k<<<dim3(DMODEL/32,  IFF/32,    LAYERS), tb>>>(fc2_w,   w2, IFF, DMODEL);
    wtr_k<<<dim3(VOCAB/32,   DMODEL/32, 1),      tb>>>(head_w,  wh, DMODEL, VOCAB);

    embed_k<<<(ELTS + 255) / 256, 256>>>(ids, embed_w, x);

    for (int l = 0; l < LAYERS; l++) {
        // ---- attention branch ----
        ln_k<<<NTOK, 256>>>(x, ln1_s + l * DMODEL, ln1_b + l * DMODEL, h);
        gemm_h<256,0,0,0,0><<<dim3(3 * DMODEL / BN_, NTOK / 256, 1), 256, S256>>>(
            h, wq + (size_t)l * DMODEL * 3 * DMODEL,
            qkv_b + (size_t)l * 3 * DMODEL, qkv,
            NTOK, 3 * DMODEL, DMODEL, 0, 0, 0, 1.f);
        rope_split_k<<<(ELTS + 255) / 256, 256>>>(qkv, Q, K);
        vt_k<<<dim3(SEQ/32, HDIM/32, BATCH*NHEAD), tb>>>(qkv, Vt);
        // scores = Q K^T / sqrt(HS), causal blocks only
        gemm_h<256,0,0,0,1><<<dim3(SEQ / BN_, SEQ / 256, BATCH * NHEAD), 256, S256>>>(
            Q, K, nullptr, sc,
            SEQ, SEQ, HDIM,
            (long long)SEQ * HDIM, (long long)SEQ * HDIM,
            (long long)SEQ * SEQ, INV_SCALE);
        softmax_k<<<BATCH * NHEAD * SEQ, 256>>>(sc, p);
        // O = P V (B = V^T [HS,T]); causal k-clamp; merged [B,T,D] half out
        gemm_h<128,0,1,1,2><<<dim3(1, SEQ / 128, BATCH * NHEAD), 128, S128>>>(
            p, Vt, nullptr, mg,
            SEQ, HDIM, SEQ,
            (long long)SEQ * SEQ, (long long)HDIM * SEQ, 0, 1.f);
        gemm_h<128,0,0,0,0><<<dim3(DMODEL / BN_, NTOK / 128, 1), 128, S128>>>(
            mg, wd + (size_t)l * DMODEL * DMODEL,
            dense_b + (size_t)l * DMODEL, ad,
            NTOK, DMODEL, DMODEL, 0, 0, 0, 1.f);
        // ---- MLP branch (on original x) ----
        ln_k<<<NTOK, 256>>>(x, ln2_s + l * DMODEL, ln2_b + l * DMODEL, h);
        gemm_h<256,1,0,1,0><<<dim3(IFF / BN_, NTOK / 256, 1), 256, S256>>>(
            h, w1 + (size_t)l * DMODEL * IFF,
            fc1_b + (size_t)l * IFF, m1,
            NTOK, IFF, DMODEL, 0, 0, 0, 1.f);
        gemm_h<128,0,0,0,0><<<dim3(DMODEL / BN_, NTOK / 128, 1), 128, S128>>>(
            m1, w2 + (size_t)l * IFF * DMODEL,
            fc2_b + (size_t)l * DMODEL, m2,
            NTOK, DMODEL, IFF, 0, 0, 0, 1.f);
        // ---- residual: x = x + attn_out + mlp_out ----
        add3_k<<<(ELTS / 4 + 255) / 256, 256>>>(x, ad, m2);
    }

    // final LN + head
    ln_k<<<NTOK, 256>>>(x, fln_s, fln_b, h);
    gemm_h<256,0,0,0,0><<<dim3(VOCAB / BN_, NTOK / 256, 1), 256, S256>>>(
        h, wh, nullptr, out,
        NTOK, VOCAB, DMODEL, 0, 0, 0, 1.f);
}

// round 13
// speedup vs baseline: 1.5273x; 1.0450x over previous
#include <cuda_runtime.h>
#include <cuda_fp16.h>
#include <math.h>

// Problem dims
#define LAYERS 6
#define DMODEL 1024
#define NHEAD  16
#define HDIM   64
#define ROTD   16
#define IFF    4096
#define VOCAB  50304
#define BATCH  2
#define SEQ    1024
#define NTOK   (BATCH*SEQ)        // 2048
#define LN_EPS 1e-5f
#define INV_SCALE 0.125f          // 1/sqrt(64)

// ---------------- scratch (static device globals; no allocation) -------------
__device__ float  g_x[NTOK*DMODEL];
__device__ __half g_h[NTOK*DMODEL];
__device__ float  g_qkv[NTOK*3*DMODEL];
__device__ __half g_q[NTOK*DMODEL];
__device__ __half g_k[NTOK*DMODEL];
__device__ __half g_vt[NTOK*DMODEL];                      // V^T per (b,h): [HS,T]
__device__ float  g_scores[(size_t)BATCH*NHEAD*SEQ*SEQ];  // 134 MB
__device__ __half g_p[(size_t)BATCH*NHEAD*SEQ*SEQ];       // probabilities, 67 MB
__device__ __half g_mg[NTOK*DMODEL];
__device__ float  g_attd[NTOK*DMODEL];
__device__ __half g_m1[NTOK*IFF];
__device__ float  g_m2[NTOK*DMODEL];

// fp16, TRANSPOSED weight copies ([N,K] layout), built once per launch
__device__ __half g_wq[(size_t)LAYERS*DMODEL*3*DMODEL];
__device__ __half g_wd[(size_t)LAYERS*DMODEL*DMODEL];
__device__ __half g_w1[(size_t)LAYERS*DMODEL*IFF];
__device__ __half g_w2[(size_t)LAYERS*IFF*DMODEL];
__device__ __half g_wh[(size_t)DMODEL*VOCAB];

// ---------------- helpers -----------------------------------------------------
__device__ __forceinline__ float blockReduceSum(float v) {
    __shared__ float sh[8];
    int lane = threadIdx.x & 31, wid = threadIdx.x >> 5;
    #pragma unroll
    for (int o = 16; o; o >>= 1) v += __shfl_xor_sync(0xffffffffu, v, o);
    if (lane == 0) sh[wid] = v;
    __syncthreads();
    float r = 0.f;
    #pragma unroll
    for (int i = 0; i < 8; i++) r += sh[i];
    __syncthreads();
    return r;
}

__device__ __forceinline__ float blockReduceMax(float v) {
    __shared__ float sh[8];
    int lane = threadIdx.x & 31, wid = threadIdx.x >> 5;
    #pragma unroll
    for (int o = 16; o; o >>= 1) v = fmaxf(v, __shfl_xor_sync(0xffffffffu, v, o));
    if (lane == 0) sh[wid] = v;
    __syncthreads();
    float r = -1e30f;
    #pragma unroll
    for (int i = 0; i < 8; i++) r = fmaxf(r, sh[i]);
    __syncthreads();
    return r;
}

__device__ __forceinline__ float gelu_exact(float x) {
    return 0.5f * x * (1.f + erff(x * 0.70710678118654752f));
}

__device__ __forceinline__ void mma16(float* c, const unsigned* a,
                                      unsigned b0, unsigned b1) {
    asm volatile(
        "mma.sync.aligned.m16n8k16.row.col.f32.f16.f16.f32 "
        "{%0,%1,%2,%3},{%4,%5,%6,%7},{%8,%9},{%0,%1,%2,%3};"
        : "+f"(c[0]), "+f"(c[1]), "+f"(c[2]), "+f"(c[3])
        : "r"(a[0]), "r"(a[1]), "r"(a[2]), "r"(a[3]), "r"(b0), "r"(b1));
}

__device__ __forceinline__ void ldsm4(unsigned* r, unsigned saddr) {
    asm volatile(
        "ldmatrix.sync.aligned.m8n8.x4.shared.b16 {%0,%1,%2,%3}, [%4];"
        : "=r"(r[0]), "=r"(r[1]), "=r"(r[2]), "=r"(r[3]) : "r"(saddr));
}

__device__ __forceinline__ void cp16h(__half* smem, const __half* g) {
    unsigned s = (unsigned)__cvta_generic_to_shared(smem);
    asm volatile("cp.async.cg.shared.global [%0], [%1], 16;\n"
                 :: "r"(s), "l"(g));
}
__device__ __forceinline__ void cpcommit() {
    asm volatile("cp.async.commit_group;\n" ::);
}
__device__ __forceinline__ void cpwait0() {
    asm volatile("cp.async.wait_group 0;\n" ::: "memory");
}

// ---------------- fp16 tensor-core GEMM:  C = alpha*A.B^T (+bias) ------------
// A [M,K] half row-major, B [N,K] half row-major.  f32 accumulate.
// TBM: CTA M-tile (256 -> 8 warps, 128 -> 4 warps).  TBN: CTA N-tile (128/64).
// Warp tile 64 x (TBN/2).  BK 32 halves, double-buffered cp.async.
// All dims must be exact tile multiples (true for every call here).
// EPI bit0: exact GELU.  OUTH: write half, else float.
// PVOUT=1: C base = (z>>4)*SEQ*D + (z&15)*HDIM, ldC = DMODEL (attention merge).
// CAUSAL=1: skip CTA if bn >= bm+TBM.  CAUSAL=2: clamp k-range to bm+TBM.
#define ASTR 40   // halves per smem row: 80B stride == 20 words -> conflict-free

template<int TBM, int TBN, int EPI, int PVOUT, int OUTH, int CAUSAL>
__global__ void __launch_bounds__(TBM, 256/TBM)
gemm_h(const __half* __restrict__ A, const __half* __restrict__ B,
       const float* __restrict__ bias, void* __restrict__ Cv,
       int M, int N, int K,
       long long sA, long long sB, long long sC, float alpha)
{
    constexpr int ABYTES = TBM * ASTR * 2;
    constexpr int BBYTES = TBN * ASTR * 2;
    constexpr int NB = TBN / 32;              // ldsmB per warp per ks (4 or 2)
    extern __shared__ __half smh[];

    const int bm = blockIdx.y * TBM;
    const int bn = blockIdx.x * TBN;
    if (CAUSAL == 1 && bn >= bm + TBM) return;   // fully masked score block

    const int bz = blockIdx.z;
    A += (long long)bz * sA;
    B += (long long)bz * sB;
    long long cbase, ldC;
    if (PVOUT) {
        cbase = (long long)(bz >> 4) * SEQ * DMODEL + (bz & 15) * HDIM;
        ldC = DMODEL;
    } else {
        cbase = (long long)bz * sC;
        ldC = N;
    }

    const int tid = threadIdx.x;
    const int lane = tid & 31, w = tid >> 5;
    const int wr = w >> 1, wc = w & 1;
    const int gid = lane >> 2, tig = lane & 3;
    const int m0 = wr * 64, n0 = wc * (TBN / 2);

    int nk = K / 32;
    if (CAUSAL == 2) { int lim = (bm + TBM) / 32; nk = nk < lim ? nk : lim; }

    float acc[4][2 * NB][4];
    #pragma unroll
    for (int i = 0; i < 4; i++)
        #pragma unroll
        for (int j = 0; j < 2 * NB; j++)
            #pragma unroll
            for (int q = 0; q < 4; q++) acc[i][j][q] = 0.f;

    auto loadT = [&](int buf, int k0) {
        #pragma unroll
        for (int i = 0; i < 4; i++) {                 // A: TBM rows x 32 halves
            int idx = i * TBM + tid;
            int r = idx >> 2, c8 = (idx & 3) * 8;
            cp16h(smh + buf * (TBM * ASTR) + r * ASTR + c8,
                  A + (long long)(bm + r) * K + k0 + c8);
        }
        #pragma unroll
        for (int i = 0; i < TBN * 4 / TBM; i++) {     // B: TBN rows x 32 halves
            int idx = i * TBM + tid;
            int r = idx >> 2, c8 = (idx & 3) * 8;
            cp16h(smh + 2 * (TBM * ASTR) + buf * (TBN * ASTR) + r * ASTR + c8,
                  B + (long long)(bn + r) * K + k0 + c8);
        }
        cpcommit();
    };

    // ldmatrix lane-relative byte offsets
    const unsigned sbase = (unsigned)__cvta_generic_to_shared(smh);
    unsigned aoff[4], boff[NB];
    {
        int rl = lane & 15, kh = (lane >> 4) * 16;
        #pragma unroll
        for (int mt = 0; mt < 4; mt++)
            aoff[mt] = (m0 + mt * 16 + rl) * (ASTR * 2) + kh;
        #pragma unroll
        for (int j = 0; j < NB; j++)
            boff[j] = (unsigned)(2 * ABYTES) + (n0 + j * 16 + rl) * (ASTR * 2) + kh;
    }

    loadT(0, 0);
    for (int t = 0; t < nk; t++) {
        cpwait0();
        __syncthreads();
        if (t + 1 < nk) loadT((t + 1) & 1, (t + 1) * 32);

        const unsigned abase = sbase + (t & 1) * ABYTES;
        const unsigned bbase = sbase + (t & 1) * BBYTES;

        #pragma unroll
        for (int ks = 0; ks < 2; ks++) {
            unsigned af[4][4];
            #pragma unroll
            for (int mt = 0; mt < 4; mt++)
                ldsm4(af[mt], abase + aoff[mt] + ks * 32);
            #pragma unroll
            for (int j = 0; j < NB; j++) {
                unsigned bf[4];
                ldsm4(bf, bbase + boff[j] + ks * 32);
                #pragma unroll
                for (int mt = 0; mt < 4; mt++) {
                    mma16(acc[mt][2*j],   af[mt], bf[0], bf[2]);
                    mma16(acc[mt][2*j+1], af[mt], bf[1], bf[3]);
                }
            }
        }
        // NOTE: no barrier here — the top-of-iteration __syncthreads() already
        // orders this compute against the load that overwrites this buffer.
    }

    // ---- epilogue ----
    #pragma unroll
    for (int mt = 0; mt < 4; mt++) {
        const int r0 = bm + m0 + mt * 16 + gid;
        #pragma unroll
        for (int nt = 0; nt < 2 * NB; nt++) {
            int c = bn + n0 + nt * 8 + 2 * tig;
            float* a4 = acc[mt][nt];
            float v0 = a4[0] * alpha, v1 = a4[1] * alpha;
            float v2 = a4[2] * alpha, v3 = a4[3] * alpha;
            if (bias) {
                float bv0 = bias[c], bv1 = bias[c + 1];
                v0 += bv0; v1 += bv1; v2 += bv0; v3 += bv1;
            }
            if (EPI & 1) {
                v0 = gelu_exact(v0); v1 = gelu_exact(v1);
                v2 = gelu_exact(v2); v3 = gelu_exact(v3);
            }
            if (OUTH) {
                __half* Ch = (__half*)Cv + cbase;
                *(__half2*)(Ch + (long long)r0 * ldC + c) =
                    __floats2half2_rn(v0, v1);
                *(__half2*)(Ch + (long long)(r0 + 8) * ldC + c) =
                    __floats2half2_rn(v2, v3);
            } else {
                float* Cf = (float*)Cv + cbase;
                *(float2*)(Cf + (long long)r0 * ldC + c) = make_float2(v0, v1);
                *(float2*)(Cf + (long long)(r0 + 8) * ldC + c) = make_float2(v2, v3);
            }
        }
    }
}

// ---------------- weight transpose f32[R][C] -> half[C][R] -------------------
__global__ void wtr_k(const float* __restrict__ in, __half* __restrict__ out,
                      int R, int C)
{
    __shared__ float t[32][33];
    in  += (size_t)blockIdx.z * R * C;
    out += (size_t)blockIdx.z * R * C;
    int r0 = blockIdx.y * 32, c0 = blockIdx.x * 32;
    #pragma unroll
    for (int i = threadIdx.y; i < 32; i += 8)
        t[i][threadIdx.x] = in[(size_t)(r0 + i) * C + c0 + threadIdx.x];
    __syncthreads();
    #pragma unroll
    for (int i = threadIdx.y; i < 32; i += 8)
        out[(size_t)(c0 + i) * R + r0 + threadIdx.x] =
            __float2half_rn(t[threadIdx.x][i]);
}

// V^T from f32 qkv: vt[(bh*HS + d)*T + t] = half(V[b,t,h,d])
__global__ void vt_k(const float* __restrict__ qkv, __half* __restrict__ vt)
{
    __shared__ float tile[32][33];
    int bh = blockIdx.z;
    int b = bh >> 4, h = bh & 15;
    int t0 = blockIdx.x * 32, d0 = blockIdx.y * 32;
    #pragma unroll
    for (int i = threadIdx.y; i < 32; i += 8) {
        int t = t0 + i;
        tile[i][threadIdx.x] = qkv[((size_t)(b * SEQ + t)) * (3 * DMODEL)
                                   + h * 3 * HDIM + 2 * HDIM + d0 + threadIdx.x];
    }
    __syncthreads();
    #pragma unroll
    for (int i = threadIdx.y; i < 32; i += 8) {
        int d = d0 + i;
        vt[((size_t)bh * HDIM + d) * SEQ + t0 + threadIdx.x] =
            __float2half_rn(tile[threadIdx.x][i]);
    }
}

// ---------------- elementwise kernels ----------------------------------------
__global__ void embed_k(const int* __restrict__ ids,
                        const float* __restrict__ ew, float* __restrict__ x)
{
    int idx = blockIdx.x * blockDim.x + threadIdx.x;
    if (idx >= NTOK * DMODEL) return;
    int row = idx / DMODEL, d = idx % DMODEL;
    x[idx] = ew[(long long)ids[row] * DMODEL + d];
}

// LayerNorm f32 -> half
__global__ void ln_k(const float* __restrict__ x, const float* __restrict__ s,
                     const float* __restrict__ b, __half* __restrict__ out)
{
    int row = blockIdx.x;
    const float4* xr = (const float4*)(x + (long long)row * DMODEL);
    float4 v = xr[threadIdx.x];
    float sum = v.x + v.y + v.z + v.w;
    float mean = blockReduceSum(sum) * (1.f / DMODEL);
    float dx = v.x - mean, dy = v.y - mean, dz = v.z - mean, dw = v.w - mean;
    float var = blockReduceSum(dx*dx + dy*dy + dz*dz + dw*dw) * (1.f / DMODEL);
    float r = rsqrtf(var + LN_EPS);
    float4 s4 = ((const float4*)s)[threadIdx.x];
    float4 b4 = ((const float4*)b)[threadIdx.x];
    __half2* orow = (__half2*)(out + (long long)row * DMODEL);
    orow[2*threadIdx.x]   = __floats2half2_rn(dx * r * s4.x + b4.x,
                                              dy * r * s4.y + b4.y);
    orow[2*threadIdx.x+1] = __floats2half2_rn(dz * r * s4.z + b4.z,
                                              dw * r * s4.w + b4.w);
}

// f32 qkv -> rope q,k -> half Q,K [B,H,T,HS]
__global__ void rope_split_k(const float* __restrict__ qkv,
                             __half* __restrict__ Q, __half* __restrict__ K)
{
    int idx = blockIdx.x * blockDim.x + threadIdx.x;
    if (idx >= NTOK * DMODEL) return;
    int d = idx & (HDIM - 1);
    int t = (idx >> 6) & (SEQ - 1);
    int h = (idx >> 16) & (NHEAD - 1);
    int b = idx >> 20;
    long long base = ((long long)(b * SEQ + t)) * (3 * DMODEL) + h * (3 * HDIM);
    float qv = qkv[base + d];
    float kv = qkv[base + HDIM + d];
    if (d < ROTD) {
        int fi = d & 7;
        float inv = expf(-(float)(2 * fi) / ROTD * logf(10000.0f));
        float ang = (float)t * inv;
        float c = cosf(ang), s = sinf(ang);
        int partner = (d < 8) ? d + 8 : d - 8;
        float qp = qkv[base + partner];
        float kp = qkv[base + HDIM + partner];
        float rq = (d < 8) ? -qp : qp;
        float rk = (d < 8) ? -kp : kp;
        qv = qv * c + rq * s;
        kv = kv * c + rk * s;
    }
    Q[idx] = __float2half_rn(qv); K[idx] = __float2half_rn(kv);
}

// causal softmax: f32 scores -> half probabilities.
// exp cached in smem; writes only up to the 128-aligned causal boundary.
__global__ void softmax_k(const float* __restrict__ sc, __half* __restrict__ p)
{
    __shared__ float ebuf[SEQ];
    long long r = blockIdx.x;
    int i = (int)(r & (SEQ - 1));
    const float* row = sc + r * SEQ;
    __half* prow = p + r * SEQ;
    int tid = threadIdx.x;
    float mx = -1e30f;
    for (int j = tid; j <= i; j += 256) mx = fmaxf(mx, row[j]);
    mx = blockReduceMax(mx);
    float sum = 0.f;
    for (int j = tid; j <= i; j += 256) {
        float e = expf(row[j] - mx);
        ebuf[j] = e;
        sum += e;
    }
    sum = blockReduceSum(sum);
    __syncthreads();
    float inv = 1.f / sum;
    int lim = ((i >> 7) + 1) << 7;           // causal PV reads keys < lim only
    for (int j = tid; j < lim; j += 256)
        prow[j] = (j <= i) ? __float2half_rn(ebuf[j] * inv)
                           : __float2half_rn(0.f);
}

// x += a + c
__global__ void add3_k(float* __restrict__ x, const float* __restrict__ a,
                       const float* __restrict__ c)
{
    int idx = blockIdx.x * blockDim.x + threadIdx.x;
    if (idx >= NTOK * DMODEL / 4) return;
    float4 xv = ((const float4*)x)[idx];
    float4 av = ((const float4*)a)[idx];
    float4 cv = ((const float4*)c)[idx];
    xv.x += av.x + cv.x; xv.y += av.y + cv.y;
    xv.z += av.z + cv.z; xv.w += av.w + cv.w;
    ((float4*)x)[idx] = xv;
}

#define S256 (2*(256*ASTR*2 + 128*ASTR*2))   // 61440
#define S128 (2*(128*ASTR*2 + 128*ASTR*2))   // 40960
#define SPV  (2*(128*ASTR*2 + 64*ASTR*2))    // 30720

// ---------------- driver ------------------------------------------------------
extern "C" void kernel_launch(void* const* d_in, const int* in_sizes, int n_in,
                              void* d_out, int out_size)
{
    const int*   ids     = (const int*)  d_in[0];
    const float* embed_w = (const float*)d_in[1];
    const float* ln1_s   = (const float*)d_in[2];
    const float* ln1_b   = (const float*)d_in[3];
    const float* ln2_s   = (const float*)d_in[4];
    const float* ln2_b   = (const float*)d_in[5];
    const float* qkv_w   = (const float*)d_in[6];
    const float* qkv_b   = (const float*)d_in[7];
    const float* dense_w = (const float*)d_in[8];
    const float* dense_b = (const float*)d_in[9];
    const float* fc1_w   = (const float*)d_in[10];
    const float* fc1_b   = (const float*)d_in[11];
    const float* fc2_w   = (const float*)d_in[12];
    const float* fc2_b   = (const float*)d_in[13];
    const float* fln_s   = (const float*)d_in[14];
    const float* fln_b   = (const float*)d_in[15];
    const float* head_w  = (const float*)d_in[16];
    float* out = (float*)d_out;

    cudaFuncSetAttribute(gemm_h<256,128,0,0,0,0>, cudaFuncAttributeMaxDynamicSharedMemorySize, S256);
    cudaFuncSetAttribute(gemm_h<256,128,0,0,0,1>, cudaFuncAttributeMaxDynamicSharedMemorySize, S256);
    cudaFuncSetAttribute(gemm_h<256,128,1,0,1,0>, cudaFuncAttributeMaxDynamicSharedMemorySize, S256);
    cudaFuncSetAttribute(gemm_h<128,64,0,1,1,2>,  cudaFuncAttributeMaxDynamicSharedMemorySize, SPV);
    cudaFuncSetAttribute(gemm_h<128,128,0,0,0,0>, cudaFuncAttributeMaxDynamicSharedMemorySize, S128);

    float *x, *qkv, *sc, *ad, *m2;
    __half *h, *Q, *K, *Vt, *p, *mg, *m1;
    __half *wq, *wd, *w1, *w2, *wh;
    cudaGetSymbolAddress((void**)&x,   g_x);
    cudaGetSymbolAddress((void**)&h,   g_h);
    cudaGetSymbolAddress((void**)&qkv, g_qkv);
    cudaGetSymbolAddress((void**)&Q,   g_q);
    cudaGetSymbolAddress((void**)&K,   g_k);
    cudaGetSymbolAddress((void**)&Vt,  g_vt);
    cudaGetSymbolAddress((void**)&sc,  g_scores);
    cudaGetSymbolAddress((void**)&p,   g_p);
    cudaGetSymbolAddress((void**)&mg,  g_mg);
    cudaGetSymbolAddress((void**)&ad,  g_attd);
    cudaGetSymbolAddress((void**)&m1,  g_m1);
    cudaGetSymbolAddress((void**)&m2,  g_m2);
    cudaGetSymbolAddress((void**)&wq,  g_wq);
    cudaGetSymbolAddress((void**)&wd,  g_wd);
    cudaGetSymbolAddress((void**)&w1,  g_w1);
    cudaGetSymbolAddress((void**)&w2,  g_w2);
    cudaGetSymbolAddress((void**)&wh,  g_wh);

    const int ELTS = NTOK * DMODEL;
    dim3 tb(32, 8);

    // ---- one-shot weight transpose + fp16 conversion ([K,N] -> [N,K]) ----
    wtr_k<<<dim3(3*DMODEL/32, DMODEL/32, LAYERS), tb>>>(qkv_w,  wq, DMODEL, 3*DMODEL);
    wtr_k<<<dim3(DMODEL/32,  DMODEL/32, LAYERS), tb>>>(dense_w, wd, DMODEL, DMODEL);
    wtr_k<<<dim3(IFF/32,     DMODEL/32, LAYERS), tb>>>(fc1_w,   w1, DMODEL, IFF);
    wtr_k<<<dim3(DMODEL/32,  IFF/32,    LAYERS), tb>>>(fc2_w,   w2, IFF, DMODEL);
    wtr_k<<<dim3(VOCAB/32,   DMODEL/32, 1),      tb>>>(head_w,  wh, DMODEL, VOCAB);

    embed_k<<<(ELTS + 255) / 256, 256>>>(ids, embed_w, x);

    for (int l = 0; l < LAYERS; l++) {
        // ---- attention branch ----
        ln_k<<<NTOK, 256>>>(x, ln1_s + l * DMODEL, ln1_b + l * DMODEL, h);
        gemm_h<256,128,0,0,0,0><<<dim3(3 * DMODEL / 128, NTOK / 256, 1), 256, S256>>>(
            h, wq + (size_t)l * DMODEL * 3 * DMODEL,
            qkv_b + (size_t)l * 3 * DMODEL, qkv,
            NTOK, 3 * DMODEL, DMODEL, 0, 0, 0, 1.f);
        rope_split_k<<<(ELTS + 255) / 256, 256>>>(qkv, Q, K);
        vt_k<<<dim3(SEQ/32, HDIM/32, BATCH*NHEAD), tb>>>(qkv, Vt);
        // scores = Q K^T / sqrt(HS), causal blocks only
        gemm_h<256,128,0,0,0,1><<<dim3(SEQ / 128, SEQ / 256, BATCH * NHEAD), 256, S256>>>(
            Q, K, nullptr, sc,
            SEQ, SEQ, HDIM,
            (long long)SEQ * HDIM, (long long)SEQ * HDIM,
            (long long)SEQ * SEQ, INV_SCALE);
        softmax_k<<<BATCH * NHEAD * SEQ, 256>>>(sc, p);
        // O = P V (B = V^T [HS,T]); causal k-clamp; merged [B,T,D] half out
        gemm_h<128,64,0,1,1,2><<<dim3(1, SEQ / 128, BATCH * NHEAD), 128, SPV>>>(
            p, Vt, nullptr, mg,
            SEQ, HDIM, SEQ,
            (long long)SEQ * SEQ, (long long)HDIM * SEQ, 0, 1.f);
        gemm_h<128,128,0,0,0,0><<<dim3(DMODEL / 128, NTOK / 128, 1), 128, S128>>>(
            mg, wd + (size_t)l * DMODEL * DMODEL,
            dense_b + (size_t)l * DMODEL, ad,
            NTOK, DMODEL, DMODEL, 0, 0, 0, 1.f);
        // ---- MLP branch (on original x) ----
        ln_k<<<NTOK, 256>>>(x, ln2_s + l * DMODEL, ln2_b + l * DMODEL, h);
        gemm_h<256,128,1,0,1,0><<<dim3(IFF / 128, NTOK / 256, 1), 256, S256>>>(
            h, w1 + (size_t)l * DMODEL * IFF,
            fc1_b + (size_t)l * IFF, m1,
            NTOK, IFF, DMODEL, 0, 0, 0, 1.f);
        gemm_h<128,128,0,0,0,0><<<dim3(DMODEL / 128, NTOK / 128, 1), 128, S128>>>(
            m1, w2 + (size_t)l * IFF * DMODEL,
            fc2_b + (size_t)l * DMODEL, m2,
            NTOK, DMODEL, IFF, 0, 0, 0, 1.f);
        // ---- residual: x = x + attn_out + mlp_out ----
        add3_k<<<(ELTS / 4 + 255) / 256, 256>>>(x, ad, m2);
    }

    // final LN + head
    ln_k<<<NTOK, 256>>>(x, fln_s, fln_b, h);
    gemm_h<256,128,0,0,0,0><<<dim3(VOCAB / 128, NTOK / 256, 1), 256, S256>>>(
        h, wh, nullptr, out,
        NTOK, VOCAB, DMODEL, 0, 0, 0, 1.f);
}

// round 14
// speedup vs baseline: 1.5858x; 1.0383x over previous
#include <cuda_runtime.h>
#include <cuda_fp16.h>
#include <math.h>

// Problem dims
#define LAYERS 6
#define DMODEL 1024
#define NHEAD  16
#define HDIM   64
#define ROTD   16
#define IFF    4096
#define VOCAB  50304
#define BATCH  2
#define SEQ    1024
#define NTOK   (BATCH*SEQ)        // 2048
#define LN_EPS 1e-5f
#define INV_SCALE 0.125f          // 1/sqrt(64)

// ---------------- scratch (static device globals; no allocation) -------------
__device__ float  g_x[NTOK*DMODEL];
__device__ __half g_h[NTOK*DMODEL];
__device__ float  g_qkv[NTOK*3*DMODEL];
__device__ __half g_q[NTOK*DMODEL];
__device__ __half g_k[NTOK*DMODEL];
__device__ __half g_vt[NTOK*DMODEL];                      // V^T per (b,h): [HS,T]
__device__ float  g_scores[(size_t)BATCH*NHEAD*SEQ*SEQ];  // 134 MB
__device__ __half g_p[(size_t)BATCH*NHEAD*SEQ*SEQ];       // probabilities, 67 MB
__device__ __half g_mg[NTOK*DMODEL];
__device__ float  g_attd[NTOK*DMODEL];
__device__ __half g_m1[NTOK*IFF];

// fp16, TRANSPOSED weight copies ([N,K] layout), built once per launch
__device__ __half g_wq[(size_t)LAYERS*DMODEL*3*DMODEL];
__device__ __half g_wd[(size_t)LAYERS*DMODEL*DMODEL];
__device__ __half g_w1[(size_t)LAYERS*DMODEL*IFF];
__device__ __half g_w2[(size_t)LAYERS*IFF*DMODEL];
__device__ __half g_wh[(size_t)DMODEL*VOCAB];

// ---------------- helpers -----------------------------------------------------
__device__ __forceinline__ float blockReduceSum(float v) {
    __shared__ float sh[8];
    int lane = threadIdx.x & 31, wid = threadIdx.x >> 5;
    #pragma unroll
    for (int o = 16; o; o >>= 1) v += __shfl_xor_sync(0xffffffffu, v, o);
    if (lane == 0) sh[wid] = v;
    __syncthreads();
    float r = 0.f;
    #pragma unroll
    for (int i = 0; i < 8; i++) r += sh[i];
    __syncthreads();
    return r;
}

__device__ __forceinline__ float blockReduceMax(float v) {
    __shared__ float sh[8];
    int lane = threadIdx.x & 31, wid = threadIdx.x >> 5;
    #pragma unroll
    for (int o = 16; o; o >>= 1) v = fmaxf(v, __shfl_xor_sync(0xffffffffu, v, o));
    if (lane == 0) sh[wid] = v;
    __syncthreads();
    float r = -1e30f;
    #pragma unroll
    for (int i = 0; i < 8; i++) r = fmaxf(r, sh[i]);
    __syncthreads();
    return r;
}

__device__ __forceinline__ float gelu_exact(float x) {
    return 0.5f * x * (1.f + erff(x * 0.70710678118654752f));
}

__device__ __forceinline__ void mma16(float* c, const unsigned* a,
                                      unsigned b0, unsigned b1) {
    asm volatile(
        "mma.sync.aligned.m16n8k16.row.col.f32.f16.f16.f32 "
        "{%0,%1,%2,%3},{%4,%5,%6,%7},{%8,%9},{%0,%1,%2,%3};"
        : "+f"(c[0]), "+f"(c[1]), "+f"(c[2]), "+f"(c[3])
        : "r"(a[0]), "r"(a[1]), "r"(a[2]), "r"(a[3]), "r"(b0), "r"(b1));
}

__device__ __forceinline__ void ldsm4(unsigned* r, unsigned saddr) {
    asm volatile(
        "ldmatrix.sync.aligned.m8n8.x4.shared.b16 {%0,%1,%2,%3}, [%4];"
        : "=r"(r[0]), "=r"(r[1]), "=r"(r[2]), "=r"(r[3]) : "r"(saddr));
}

__device__ __forceinline__ void cp16h(__half* smem, const __half* g) {
    unsigned s = (unsigned)__cvta_generic_to_shared(smem);
    asm volatile("cp.async.cg.shared.global [%0], [%1], 16;\n"
                 :: "r"(s), "l"(g));
}
__device__ __forceinline__ void cpcommit() {
    asm volatile("cp.async.commit_group;\n" ::);
}
__device__ __forceinline__ void cpwait0() {
    asm volatile("cp.async.wait_group 0;\n" ::: "memory");
}

// ---------------- fp16 tensor-core GEMM:  C = alpha*A.B^T (+bias) ------------
// A [M,K] half row-major, B [N,K] half row-major.  f32 accumulate.
// TBM: CTA M-tile (256 -> 8 warps, 128 -> 4 warps).  TBN: CTA N-tile (128/64).
// Warp tile 64 x (TBN/2).  BK 32 halves, double-buffered cp.async.
// All dims must be exact tile multiples (true for every call here).
// EPI bit0: exact GELU.  OUTH: write half, else float.
// PVOUT=1: C base = (z>>4)*SEQ*D + (z&15)*HDIM, ldC = DMODEL (attention merge).
// CAUSAL=1: skip CTA if bn >= bm+TBM.  CAUSAL=2: clamp k-range to bm+TBM.
// RES=1: add res1[r*ldC+c] + res2[r*ldC+c] in epilogue (f32 residual fusion).
#define ASTR 40   // halves per smem row: 80B stride == 20 words -> conflict-free

template<int TBM, int TBN, int EPI, int PVOUT, int OUTH, int CAUSAL, int RES>
__global__ void __launch_bounds__(TBM, 256/TBM)
gemm_h(const __half* __restrict__ A, const __half* __restrict__ B,
       const float* __restrict__ bias,
       const float* __restrict__ res1, const float* __restrict__ res2,
       void* __restrict__ Cv,
       int M, int N, int K,
       long long sA, long long sB, long long sC, float alpha)
{
    constexpr int ABYTES = TBM * ASTR * 2;
    constexpr int BBYTES = TBN * ASTR * 2;
    constexpr int NB = TBN / 32;              // ldsmB per warp per ks (4 or 2)
    extern __shared__ __half smh[];

    const int bm = blockIdx.y * TBM;
    const int bn = blockIdx.x * TBN;
    if (CAUSAL == 1 && bn >= bm + TBM) return;   // fully masked score block

    const int bz = blockIdx.z;
    A += (long long)bz * sA;
    B += (long long)bz * sB;
    long long cbase, ldC;
    if (PVOUT) {
        cbase = (long long)(bz >> 4) * SEQ * DMODEL + (bz & 15) * HDIM;
        ldC = DMODEL;
    } else {
        cbase = (long long)bz * sC;
        ldC = N;
    }

    const int tid = threadIdx.x;
    const int lane = tid & 31, w = tid >> 5;
    const int wr = w >> 1, wc = w & 1;
    const int gid = lane >> 2, tig = lane & 3;
    const int m0 = wr * 64, n0 = wc * (TBN / 2);

    int nk = K / 32;
    if (CAUSAL == 2) { int lim = (bm + TBM) / 32; nk = nk < lim ? nk : lim; }

    float acc[4][2 * NB][4];
    #pragma unroll
    for (int i = 0; i < 4; i++)
        #pragma unroll
        for (int j = 0; j < 2 * NB; j++)
            #pragma unroll
            for (int q = 0; q < 4; q++) acc[i][j][q] = 0.f;

    auto loadT = [&](int buf, int k0) {
        #pragma unroll
        for (int i = 0; i < 4; i++) {                 // A: TBM rows x 32 halves
            int idx = i * TBM + tid;
            int r = idx >> 2, c8 = (idx & 3) * 8;
            cp16h(smh + buf * (TBM * ASTR) + r * ASTR + c8,
                  A + (long long)(bm + r) * K + k0 + c8);
        }
        #pragma unroll
        for (int i = 0; i < TBN * 4 / TBM; i++) {     // B: TBN rows x 32 halves
            int idx = i * TBM + tid;
            int r = idx >> 2, c8 = (idx & 3) * 8;
            cp16h(smh + 2 * (TBM * ASTR) + buf * (TBN * ASTR) + r * ASTR + c8,
                  B + (long long)(bn + r) * K + k0 + c8);
        }
        cpcommit();
    };

    // ldmatrix lane-relative byte offsets
    const unsigned sbase = (unsigned)__cvta_generic_to_shared(smh);
    unsigned aoff[4], boff[NB];
    {
        int rl = lane & 15, kh = (lane >> 4) * 16;
        #pragma unroll
        for (int mt = 0; mt < 4; mt++)
            aoff[mt] = (m0 + mt * 16 + rl) * (ASTR * 2) + kh;
        #pragma unroll
        for (int j = 0; j < NB; j++)
            boff[j] = (unsigned)(2 * ABYTES) + (n0 + j * 16 + rl) * (ASTR * 2) + kh;
    }

    loadT(0, 0);
    for (int t = 0; t < nk; t++) {
        cpwait0();
        __syncthreads();
        if (t + 1 < nk) loadT((t + 1) & 1, (t + 1) * 32);

        const unsigned abase = sbase + (t & 1) * ABYTES;
        const unsigned bbase = sbase + (t & 1) * BBYTES;

        #pragma unroll
        for (int ks = 0; ks < 2; ks++) {
            unsigned af[4][4];
            #pragma unroll
            for (int mt = 0; mt < 4; mt++)
                ldsm4(af[mt], abase + aoff[mt] + ks * 32);
            #pragma unroll
            for (int j = 0; j < NB; j++) {
                unsigned bf[4];
                ldsm4(bf, bbase + boff[j] + ks * 32);
                #pragma unroll
                for (int mt = 0; mt < 4; mt++) {
                    mma16(acc[mt][2*j],   af[mt], bf[0], bf[2]);
                    mma16(acc[mt][2*j+1], af[mt], bf[1], bf[3]);
                }
            }
        }
        // no bottom barrier — top-of-iteration sync orders buffer reuse
    }

    // ---- epilogue ----
    #pragma unroll
    for (int mt = 0; mt < 4; mt++) {
        const int r0 = bm + m0 + mt * 16 + gid;
        #pragma unroll
        for (int nt = 0; nt < 2 * NB; nt++) {
            int c = bn + n0 + nt * 8 + 2 * tig;
            float* a4 = acc[mt][nt];
            float v0 = a4[0] * alpha, v1 = a4[1] * alpha;
            float v2 = a4[2] * alpha, v3 = a4[3] * alpha;
            if (bias) {
                float bv0 = bias[c], bv1 = bias[c + 1];
                v0 += bv0; v1 += bv1; v2 += bv0; v3 += bv1;
            }
            if (EPI & 1) {
                v0 = gelu_exact(v0); v1 = gelu_exact(v1);
                v2 = gelu_exact(v2); v3 = gelu_exact(v3);
            }
            if (RES) {
                float2 ra0 = *(const float2*)(res1 + (long long)r0 * ldC + c);
                float2 ra1 = *(const float2*)(res1 + (long long)(r0 + 8) * ldC + c);
                float2 rb0 = *(const float2*)(res2 + (long long)r0 * ldC + c);
                float2 rb1 = *(const float2*)(res2 + (long long)(r0 + 8) * ldC + c);
                v0 += ra0.x + rb0.x; v1 += ra0.y + rb0.y;
                v2 += ra1.x + rb1.x; v3 += ra1.y + rb1.y;
            }
            if (OUTH) {
                __half* Ch = (__half*)Cv + cbase;
                *(__half2*)(Ch + (long long)r0 * ldC + c) =
                    __floats2half2_rn(v0, v1);
                *(__half2*)(Ch + (long long)(r0 + 8) * ldC + c) =
                    __floats2half2_rn(v2, v3);
            } else {
                float* Cf = (float*)Cv + cbase;
                *(float2*)(Cf + (long long)r0 * ldC + c) = make_float2(v0, v1);
                *(float2*)(Cf + (long long)(r0 + 8) * ldC + c) = make_float2(v2, v3);
            }
        }
    }
}

// ---------------- weight transpose f32[R][C] -> half[C][R] -------------------
// 64x64 tiles, 256 threads, float4 reads, half2 coalesced writes.
__global__ void wtr_k(const float* __restrict__ in, __half* __restrict__ out,
                      int R, int C)
{
    __shared__ float t[64][65];
    in  += (size_t)blockIdx.z * R * C;
    out += (size_t)blockIdx.z * R * C;
    int r0 = blockIdx.y * 64, c0 = blockIdx.x * 64;
    #pragma unroll
    for (int i = 0; i < 4; i++) {
        int idx = i * 256 + threadIdx.x;
        int r = idx >> 4, f = (idx & 15) * 4;
        float4 v = *(const float4*)(in + (size_t)(r0 + r) * C + c0 + f);
        t[r][f + 0] = v.x; t[r][f + 1] = v.y;
        t[r][f + 2] = v.z; t[r][f + 3] = v.w;
    }
    __syncthreads();
    #pragma unroll
    for (int i = 0; i < 8; i++) {
        int idx = i * 256 + threadIdx.x;
        int c = idx >> 5, rp = (idx & 31) * 2;
        __half2 hv = __floats2half2_rn(t[rp][c], t[rp + 1][c]);
        *(__half2*)(out + (size_t)(c0 + c) * R + r0 + rp) = hv;
    }
}

// V^T from f32 qkv: vt[(bh*HS + d)*T + t] = half(V[b,t,h,d])
__global__ void vt_k(const float* __restrict__ qkv, __half* __restrict__ vt)
{
    __shared__ float tile[32][33];
    int bh = blockIdx.z;
    int b = bh >> 4, h = bh & 15;
    int t0 = blockIdx.x * 32, d0 = blockIdx.y * 32;
    #pragma unroll
    for (int i = threadIdx.y; i < 32; i += 8) {
        int t = t0 + i;
        tile[i][threadIdx.x] = qkv[((size_t)(b * SEQ + t)) * (3 * DMODEL)
                                   + h * 3 * HDIM + 2 * HDIM + d0 + threadIdx.x];
    }
    __syncthreads();
    #pragma unroll
    for (int i = threadIdx.y; i < 32; i += 8) {
        int d = d0 + i;
        vt[((size_t)bh * HDIM + d) * SEQ + t0 + threadIdx.x] =
            __float2half_rn(tile[threadIdx.x][i]);
    }
}

// ---------------- elementwise kernels ----------------------------------------
__global__ void embed_k(const int* __restrict__ ids,
                        const float* __restrict__ ew, float* __restrict__ x)
{
    int idx = blockIdx.x * blockDim.x + threadIdx.x;
    if (idx >= NTOK * DMODEL) return;
    int row = idx / DMODEL, d = idx % DMODEL;
    x[idx] = ew[(long long)ids[row] * DMODEL + d];
}

// LayerNorm f32 -> half
__global__ void ln_k(const float* __restrict__ x, const float* __restrict__ s,
                     const float* __restrict__ b, __half* __restrict__ out)
{
    int row = blockIdx.x;
    const float4* xr = (const float4*)(x + (long long)row * DMODEL);
    float4 v = xr[threadIdx.x];
    float sum = v.x + v.y + v.z + v.w;
    float mean = blockReduceSum(sum) * (1.f / DMODEL);
    float dx = v.x - mean, dy = v.y - mean, dz = v.z - mean, dw = v.w - mean;
    float var = blockReduceSum(dx*dx + dy*dy + dz*dz + dw*dw) * (1.f / DMODEL);
    float r = rsqrtf(var + LN_EPS);
    float4 s4 = ((const float4*)s)[threadIdx.x];
    float4 b4 = ((const float4*)b)[threadIdx.x];
    __half2* orow = (__half2*)(out + (long long)row * DMODEL);
    orow[2*threadIdx.x]   = __floats2half2_rn(dx * r * s4.x + b4.x,
                                              dy * r * s4.y + b4.y);
    orow[2*threadIdx.x+1] = __floats2half2_rn(dz * r * s4.z + b4.z,
                                              dw * r * s4.w + b4.w);
}

// f32 qkv -> rope q,k -> half Q,K [B,H,T,HS]
__global__ void rope_split_k(const float* __restrict__ qkv,
                             __half* __restrict__ Q, __half* __restrict__ K)
{
    int idx = blockIdx.x * blockDim.x + threadIdx.x;
    if (idx >= NTOK * DMODEL) return;
    int d = idx & (HDIM - 1);
    int t = (idx >> 6) & (SEQ - 1);
    int h = (idx >> 16) & (NHEAD - 1);
    int b = idx >> 20;
    long long base = ((long long)(b * SEQ + t)) * (3 * DMODEL) + h * (3 * HDIM);
    float qv = qkv[base + d];
    float kv = qkv[base + HDIM + d];
    if (d < ROTD) {
        int fi = d & 7;
        float inv = expf(-(float)(2 * fi) / ROTD * logf(10000.0f));
        float ang = (float)t * inv;
        float c = cosf(ang), s = sinf(ang);
        int partner = (d < 8) ? d + 8 : d - 8;
        float qp = qkv[base + partner];
        float kp = qkv[base + HDIM + partner];
        float rq = (d < 8) ? -qp : qp;
        float rk = (d < 8) ? -kp : kp;
        qv = qv * c + rq * s;
        kv = kv * c + rk * s;
    }
    Q[idx] = __float2half_rn(qv); K[idx] = __float2half_rn(kv);
}

// causal softmax: f32 scores -> half probabilities.
// exp cached in smem; writes only up to the 128-aligned causal boundary.
__global__ void softmax_k(const float* __restrict__ sc, __half* __restrict__ p)
{
    __shared__ float ebuf[SEQ];
    long long r = blockIdx.x;
    int i = (int)(r & (SEQ - 1));
    const float* row = sc + r * SEQ;
    __half* prow = p + r * SEQ;
    int tid = threadIdx.x;
    float mx = -1e30f;
    for (int j = tid; j <= i; j += 256) mx = fmaxf(mx, row[j]);
    mx = blockReduceMax(mx);
    float sum = 0.f;
    for (int j = tid; j <= i; j += 256) {
        float e = expf(row[j] - mx);
        ebuf[j] = e;
        sum += e;
    }
    sum = blockReduceSum(sum);
    __syncthreads();
    float inv = 1.f / sum;
    int lim = ((i >> 7) + 1) << 7;           // causal PV reads keys < lim only
    for (int j = tid; j < lim; j += 256)
        prow[j] = (j <= i) ? __float2half_rn(ebuf[j] * inv)
                           : __float2half_rn(0.f);
}

#define S256 (2*(256*ASTR*2 + 128*ASTR*2))   // 61440
#define S128 (2*(128*ASTR*2 + 128*ASTR*2))   // 40960
#define SPV  (2*(128*ASTR*2 + 64*ASTR*2))    // 30720

// ---------------- driver ------------------------------------------------------
extern "C" void kernel_launch(void* const* d_in, const int* in_sizes, int n_in,
                              void* d_out, int out_size)
{
    const int*   ids     = (const int*)  d_in[0];
    const float* embed_w = (const float*)d_in[1];
    const float* ln1_s   = (const float*)d_in[2];
    const float* ln1_b   = (const float*)d_in[3];
    const float* ln2_s   = (const float*)d_in[4];
    const float* ln2_b   = (const float*)d_in[5];
    const float* qkv_w   = (const float*)d_in[6];
    const float* qkv_b   = (const float*)d_in[7];
    const float* dense_w = (const float*)d_in[8];
    const float* dense_b = (const float*)d_in[9];
    const float* fc1_w   = (const float*)d_in[10];
    const float* fc1_b   = (const float*)d_in[11];
    const float* fc2_w   = (const float*)d_in[12];
    const float* fc2_b   = (const float*)d_in[13];
    const float* fln_s   = (const float*)d_in[14];
    const float* fln_b   = (const float*)d_in[15];
    const float* head_w  = (const float*)d_in[16];
    float* out = (float*)d_out;

    cudaFuncSetAttribute(gemm_h<256,128,0,0,0,0,0>, cudaFuncAttributeMaxDynamicSharedMemorySize, S256);
    cudaFuncSetAttribute(gemm_h<256,128,0,0,0,1,0>, cudaFuncAttributeMaxDynamicSharedMemorySize, S256);
    cudaFuncSetAttribute(gemm_h<256,128,1,0,1,0,0>, cudaFuncAttributeMaxDynamicSharedMemorySize, S256);
    cudaFuncSetAttribute(gemm_h<128,64,0,1,1,2,0>,  cudaFuncAttributeMaxDynamicSharedMemorySize, SPV);
    cudaFuncSetAttribute(gemm_h<128,128,0,0,0,0,0>, cudaFuncAttributeMaxDynamicSharedMemorySize, S128);
    cudaFuncSetAttribute(gemm_h<128,128,0,0,0,0,1>, cudaFuncAttributeMaxDynamicSharedMemorySize, S128);

    float *x, *qkv, *sc, *ad;
    __half *h, *Q, *K, *Vt, *p, *mg, *m1;
    __half *wq, *wd, *w1, *w2, *wh;
    cudaGetSymbolAddress((void**)&x,   g_x);
    cudaGetSymbolAddress((void**)&h,   g_h);
    cudaGetSymbolAddress((void**)&qkv, g_qkv);
    cudaGetSymbolAddress((void**)&Q,   g_q);
    cudaGetSymbolAddress((void**)&K,   g_k);
    cudaGetSymbolAddress((void**)&Vt,  g_vt);
    cudaGetSymbolAddress((void**)&sc,  g_scores);
    cudaGetSymbolAddress((void**)&p,   g_p);
    cudaGetSymbolAddress((void**)&mg,  g_mg);
    cudaGetSymbolAddress((void**)&ad,  g_attd);
    cudaGetSymbolAddress((void**)&m1,  g_m1);
    cudaGetSymbolAddress((void**)&wq,  g_wq);
    cudaGetSymbolAddress((void**)&wd,  g_wd);
    cudaGetSymbolAddress((void**)&w1,  g_w1);
    cudaGetSymbolAddress((void**)&w2,  g_w2);
    cudaGetSymbolAddress((void**)&wh,  g_wh);

    const int ELTS = NTOK * DMODEL;
    dim3 tb(32, 8);

    // ---- one-shot weight transpose + fp16 conversion ([K,N] -> [N,K]) ----
    wtr_k<<<dim3(3*DMODEL/64, DMODEL/64, LAYERS), 256>>>(qkv_w,  wq, DMODEL, 3*DMODEL);
    wtr_k<<<dim3(DMODEL/64,  DMODEL/64, LAYERS), 256>>>(dense_w, wd, DMODEL, DMODEL);
    wtr_k<<<dim3(IFF/64,     DMODEL/64, LAYERS), 256>>>(fc1_w,   w1, DMODEL, IFF);
    wtr_k<<<dim3(DMODEL/64,  IFF/64,    LAYERS), 256>>>(fc2_w,   w2, IFF, DMODEL);
    wtr_k<<<dim3(VOCAB/64,   DMODEL/64, 1),      256>>>(head_w,  wh, DMODEL, VOCAB);

    embed_k<<<(ELTS + 255) / 256, 256>>>(ids, embed_w, x);

    for (int l = 0; l < LAYERS; l++) {
        // ---- attention branch ----
        ln_k<<<NTOK, 256>>>(x, ln1_s + l * DMODEL, ln1_b + l * DMODEL, h);
        gemm_h<256,128,0,0,0,0,0><<<dim3(3 * DMODEL / 128, NTOK / 256, 1), 256, S256>>>(
            h, wq + (size_t)l * DMODEL * 3 * DMODEL,
            qkv_b + (size_t)l * 3 * DMODEL, nullptr, nullptr, qkv,
            NTOK, 3 * DMODEL, DMODEL, 0, 0, 0, 1.f);
        rope_split_k<<<(ELTS + 255) / 256, 256>>>(qkv, Q, K);
        vt_k<<<dim3(SEQ/32, HDIM/32, BATCH*NHEAD), tb>>>(qkv, Vt);
        // scores = Q K^T / sqrt(HS), causal blocks only
        gemm_h<256,128,0,0,0,1,0><<<dim3(SEQ / 128, SEQ / 256, BATCH * NHEAD), 256, S256>>>(
            Q, K, nullptr, nullptr, nullptr, sc,
            SEQ, SEQ, HDIM,
            (long long)SEQ * HDIM, (long long)SEQ * HDIM,
            (long long)SEQ * SEQ, INV_SCALE);
        softmax_k<<<BATCH * NHEAD * SEQ, 256>>>(sc, p);
        // O = P V (B = V^T [HS,T]); causal k-clamp; merged [B,T,D] half out
        gemm_h<128,64,0,1,1,2,0><<<dim3(1, SEQ / 128, BATCH * NHEAD), 128, SPV>>>(
            p, Vt, nullptr, nullptr, nullptr, mg,
            SEQ, HDIM, SEQ,
            (long long)SEQ * SEQ, (long long)HDIM * SEQ, 0, 1.f);
        gemm_h<128,128,0,0,0,0,0><<<dim3(DMODEL / 128, NTOK / 128, 1), 128, S128>>>(
            mg, wd + (size_t)l * DMODEL * DMODEL,
            dense_b + (size_t)l * DMODEL, nullptr, nullptr, ad,
            NTOK, DMODEL, DMODEL, 0, 0, 0, 1.f);
        // ---- MLP branch (on original x) ----
        ln_k<<<NTOK, 256>>>(x, ln2_s + l * DMODEL, ln2_b + l * DMODEL, h);
        gemm_h<256,128,1,0,1,0,0><<<dim3(IFF / 128, NTOK / 256, 1), 256, S256>>>(
            h, w1 + (size_t)l * DMODEL * IFF,
            fc1_b + (size_t)l * IFF, nullptr, nullptr, m1,
            NTOK, IFF, DMODEL, 0, 0, 0, 1.f);
        // fc2 with fused residual: x = fc2(m1) + bias + x + ad
        gemm_h<128,128,0,0,0,0,1><<<dim3(DMODEL / 128, NTOK / 128, 1), 128, S128>>>(
            m1, w2 + (size_t)l * IFF * DMODEL,
            fc2_b + (size_t)l * DMODEL, x, ad, x,
            NTOK, DMODEL, IFF, 0, 0, 0, 1.f);
    }

    // final LN + head
    ln_k<<<NTOK, 256>>>(x, fln_s, fln_b, h);
    gemm_h<256,128,0,0,0,0,0><<<dim3(VOCAB / 128, NTOK / 256, 1), 256, S256>>>(
        h, wh, nullptr, nullptr, nullptr, out,
        NTOK, VOCAB, DMODEL, 0, 0, 0, 1.f);
}

// round 15
// speedup vs baseline: 1.6052x; 1.0123x over previous
#include <cuda_runtime.h>
#include <cuda_fp16.h>
#include <math.h>

// Problem dims
#define LAYERS 6
#define DMODEL 1024
#define NHEAD  16
#define HDIM   64
#define ROTD   16
#define IFF    4096
#define VOCAB  50304
#define BATCH  2
#define SEQ    1024
#define NTOK   (BATCH*SEQ)        // 2048
#define LN_EPS 1e-5f
#define INV_SCALE 0.125f          // 1/sqrt(64)

// ---------------- scratch (static device globals; no allocation) -------------
__device__ float  g_x[NTOK*DMODEL];
__device__ __half g_h[NTOK*DMODEL];
__device__ float  g_qkv[NTOK*3*DMODEL];
__device__ __half g_q[NTOK*DMODEL];
__device__ __half g_k[NTOK*DMODEL];
__device__ __half g_vt[NTOK*DMODEL];                      // V^T per (b,h): [HS,T]
__device__ float  g_scores[(size_t)BATCH*NHEAD*SEQ*SEQ];  // 134 MB
__device__ __half g_p[(size_t)BATCH*NHEAD*SEQ*SEQ];       // probabilities, 67 MB
__device__ __half g_mg[NTOK*DMODEL];
__device__ float  g_attd[NTOK*DMODEL];
__device__ __half g_m1[NTOK*IFF];

// fp16, TRANSPOSED weight copies ([N,K] layout), built once per launch
__device__ __half g_wq[(size_t)LAYERS*DMODEL*3*DMODEL];
__device__ __half g_wd[(size_t)LAYERS*DMODEL*DMODEL];
__device__ __half g_w1[(size_t)LAYERS*DMODEL*IFF];
__device__ __half g_w2[(size_t)LAYERS*IFF*DMODEL];
__device__ __half g_wh[(size_t)DMODEL*VOCAB];

// ---------------- helpers -----------------------------------------------------
__device__ __forceinline__ float blockReduceSum(float v) {
    __shared__ float sh[8];
    int lane = threadIdx.x & 31, wid = threadIdx.x >> 5;
    #pragma unroll
    for (int o = 16; o; o >>= 1) v += __shfl_xor_sync(0xffffffffu, v, o);
    if (lane == 0) sh[wid] = v;
    __syncthreads();
    float r = 0.f;
    #pragma unroll
    for (int i = 0; i < 8; i++) r += sh[i];
    __syncthreads();
    return r;
}

__device__ __forceinline__ float blockReduceMax(float v) {
    __shared__ float sh[8];
    int lane = threadIdx.x & 31, wid = threadIdx.x >> 5;
    #pragma unroll
    for (int o = 16; o; o >>= 1) v = fmaxf(v, __shfl_xor_sync(0xffffffffu, v, o));
    if (lane == 0) sh[wid] = v;
    __syncthreads();
    float r = -1e30f;
    #pragma unroll
    for (int i = 0; i < 8; i++) r = fmaxf(r, sh[i]);
    __syncthreads();
    return r;
}

__device__ __forceinline__ float gelu_exact(float x) {
    return 0.5f * x * (1.f + erff(x * 0.70710678118654752f));
}

__device__ __forceinline__ void mma16(float* c, const unsigned* a,
                                      unsigned b0, unsigned b1) {
    asm volatile(
        "mma.sync.aligned.m16n8k16.row.col.f32.f16.f16.f32 "
        "{%0,%1,%2,%3},{%4,%5,%6,%7},{%8,%9},{%0,%1,%2,%3};"
        : "+f"(c[0]), "+f"(c[1]), "+f"(c[2]), "+f"(c[3])
        : "r"(a[0]), "r"(a[1]), "r"(a[2]), "r"(a[3]), "r"(b0), "r"(b1));
}

__device__ __forceinline__ void ldsm4(unsigned* r, unsigned saddr) {
    asm volatile(
        "ldmatrix.sync.aligned.m8n8.x4.shared.b16 {%0,%1,%2,%3}, [%4];"
        : "=r"(r[0]), "=r"(r[1]), "=r"(r[2]), "=r"(r[3]) : "r"(saddr));
}

__device__ __forceinline__ void cp16h(__half* smem, const __half* g) {
    unsigned s = (unsigned)__cvta_generic_to_shared(smem);
    asm volatile("cp.async.cg.shared.global [%0], [%1], 16;\n"
                 :: "r"(s), "l"(g));
}
__device__ __forceinline__ void cpcommit() {
    asm volatile("cp.async.commit_group;\n" ::);
}
__device__ __forceinline__ void cpwait0() {
    asm volatile("cp.async.wait_group 0;\n" ::: "memory");
}

// ---------------- fp16 tensor-core GEMM:  C = alpha*A.B^T (+bias) ------------
// A [M,K] half row-major, B [N,K] half row-major.  f32 accumulate.
// TBM: CTA M-tile (256 -> 8 warps, 128 -> 4 warps).  TBN: CTA N-tile (128/64).
// Warp tile 64 x (TBN/2).  BK 32 halves, double-buffered cp.async.
// All dims must be exact tile multiples (true for every call here).
// EPI bit0: exact GELU.  OUTH: write half, else float.
// PVOUT=1: C base = (z>>4)*SEQ*D + (z&15)*HDIM, ldC = DMODEL (attention merge).
// CAUSAL=1: skip CTA if bn >= bm+TBM.  CAUSAL=2: clamp k-range to bm+TBM.
// RES=1: add res1[r*ldC+c] + res2[r*ldC+c] in epilogue (f32 residual fusion).
#define ASTR 40   // halves per smem row: 80B stride == 20 words -> conflict-free

template<int TBM, int TBN, int EPI, int PVOUT, int OUTH, int CAUSAL, int RES>
__global__ void __launch_bounds__(TBM, 256/TBM)
gemm_h(const __half* __restrict__ A, const __half* __restrict__ B,
       const float* __restrict__ bias,
       const float* __restrict__ res1, const float* __restrict__ res2,
       void* __restrict__ Cv,
       int M, int N, int K,
       long long sA, long long sB, long long sC, float alpha)
{
    constexpr int ABYTES = TBM * ASTR * 2;
    constexpr int BBYTES = TBN * ASTR * 2;
    constexpr int NB = TBN / 32;              // ldsmB per warp per ks (4 or 2)
    extern __shared__ __half smh[];

    const int bm = blockIdx.y * TBM;
    const int bn = blockIdx.x * TBN;
    if (CAUSAL == 1 && bn >= bm + TBM) return;   // fully masked score block

    const int bz = blockIdx.z;
    A += (long long)bz * sA;
    B += (long long)bz * sB;
    long long cbase, ldC;
    if (PVOUT) {
        cbase = (long long)(bz >> 4) * SEQ * DMODEL + (bz & 15) * HDIM;
        ldC = DMODEL;
    } else {
        cbase = (long long)bz * sC;
        ldC = N;
    }

    const int tid = threadIdx.x;
    const int lane = tid & 31, w = tid >> 5;
    const int wr = w >> 1, wc = w & 1;
    const int gid = lane >> 2, tig = lane & 3;
    const int m0 = wr * 64, n0 = wc * (TBN / 2);

    int nk = K / 32;
    if (CAUSAL == 2) { int lim = (bm + TBM) / 32; nk = nk < lim ? nk : lim; }

    float acc[4][2 * NB][4];
    #pragma unroll
    for (int i = 0; i < 4; i++)
        #pragma unroll
        for (int j = 0; j < 2 * NB; j++)
            #pragma unroll
            for (int q = 0; q < 4; q++) acc[i][j][q] = 0.f;

    auto loadT = [&](int buf, int k0) {
        #pragma unroll
        for (int i = 0; i < 4; i++) {                 // A: TBM rows x 32 halves
            int idx = i * TBM + tid;
            int r = idx >> 2, c8 = (idx & 3) * 8;
            cp16h(smh + buf * (TBM * ASTR) + r * ASTR + c8,
                  A + (long long)(bm + r) * K + k0 + c8);
        }
        #pragma unroll
        for (int i = 0; i < TBN * 4 / TBM; i++) {     // B: TBN rows x 32 halves
            int idx = i * TBM + tid;
            int r = idx >> 2, c8 = (idx & 3) * 8;
            cp16h(smh + 2 * (TBM * ASTR) + buf * (TBN * ASTR) + r * ASTR + c8,
                  B + (long long)(bn + r) * K + k0 + c8);
        }
        cpcommit();
    };

    // ldmatrix lane-relative byte offsets
    const unsigned sbase = (unsigned)__cvta_generic_to_shared(smh);
    unsigned aoff[4], boff[NB];
    {
        int rl = lane & 15, kh = (lane >> 4) * 16;
        #pragma unroll
        for (int mt = 0; mt < 4; mt++)
            aoff[mt] = (m0 + mt * 16 + rl) * (ASTR * 2) + kh;
        #pragma unroll
        for (int j = 0; j < NB; j++)
            boff[j] = (unsigned)(2 * ABYTES) + (n0 + j * 16 + rl) * (ASTR * 2) + kh;
    }

    loadT(0, 0);
    for (int t = 0; t < nk; t++) {
        cpwait0();
        __syncthreads();
        if (t + 1 < nk) loadT((t + 1) & 1, (t + 1) * 32);

        const unsigned abase = sbase + (t & 1) * ABYTES;
        const unsigned bbase = sbase + (t & 1) * BBYTES;

        #pragma unroll
        for (int ks = 0; ks < 2; ks++) {
            unsigned af[4][4];
            #pragma unroll
            for (int mt = 0; mt < 4; mt++)
                ldsm4(af[mt], abase + aoff[mt] + ks * 32);
            #pragma unroll
            for (int j = 0; j < NB; j++) {
                unsigned bf[4];
                ldsm4(bf, bbase + boff[j] + ks * 32);
                #pragma unroll
                for (int mt = 0; mt < 4; mt++) {
                    mma16(acc[mt][2*j],   af[mt], bf[0], bf[2]);
                    mma16(acc[mt][2*j+1], af[mt], bf[1], bf[3]);
                }
            }
        }
        // no bottom barrier — top-of-iteration sync orders buffer reuse
    }

    // ---- epilogue ----
    #pragma unroll
    for (int mt = 0; mt < 4; mt++) {
        const int r0 = bm + m0 + mt * 16 + gid;
        #pragma unroll
        for (int nt = 0; nt < 2 * NB; nt++) {
            int c = bn + n0 + nt * 8 + 2 * tig;
            float* a4 = acc[mt][nt];
            float v0 = a4[0] * alpha, v1 = a4[1] * alpha;
            float v2 = a4[2] * alpha, v3 = a4[3] * alpha;
            if (bias) {
                float bv0 = bias[c], bv1 = bias[c + 1];
                v0 += bv0; v1 += bv1; v2 += bv0; v3 += bv1;
            }
            if (EPI & 1) {
                v0 = gelu_exact(v0); v1 = gelu_exact(v1);
                v2 = gelu_exact(v2); v3 = gelu_exact(v3);
            }
            if (RES) {
                float2 ra0 = *(const float2*)(res1 + (long long)r0 * ldC + c);
                float2 ra1 = *(const float2*)(res1 + (long long)(r0 + 8) * ldC + c);
                float2 rb0 = *(const float2*)(res2 + (long long)r0 * ldC + c);
                float2 rb1 = *(const float2*)(res2 + (long long)(r0 + 8) * ldC + c);
                v0 += ra0.x + rb0.x; v1 += ra0.y + rb0.y;
                v2 += ra1.x + rb1.x; v3 += ra1.y + rb1.y;
            }
            if (OUTH) {
                __half* Ch = (__half*)Cv + cbase;
                *(__half2*)(Ch + (long long)r0 * ldC + c) =
                    __floats2half2_rn(v0, v1);
                *(__half2*)(Ch + (long long)(r0 + 8) * ldC + c) =
                    __floats2half2_rn(v2, v3);
            } else {
                float* Cf = (float*)Cv + cbase;
                *(float2*)(Cf + (long long)r0 * ldC + c) = make_float2(v0, v1);
                *(float2*)(Cf + (long long)(r0 + 8) * ldC + c) = make_float2(v2, v3);
            }
        }
    }
}

// ---------------- weight transpose f32[R][C] -> half[C][R] -------------------
// 64x64 tiles, 256 threads, float4 reads, half2 coalesced writes.
__global__ void wtr_k(const float* __restrict__ in, __half* __restrict__ out,
                      int R, int C)
{
    __shared__ float t[64][65];
    in  += (size_t)blockIdx.z * R * C;
    out += (size_t)blockIdx.z * R * C;
    int r0 = blockIdx.y * 64, c0 = blockIdx.x * 64;
    #pragma unroll
    for (int i = 0; i < 4; i++) {
        int idx = i * 256 + threadIdx.x;
        int r = idx >> 4, f = (idx & 15) * 4;
        float4 v = *(const float4*)(in + (size_t)(r0 + r) * C + c0 + f);
        t[r][f + 0] = v.x; t[r][f + 1] = v.y;
        t[r][f + 2] = v.z; t[r][f + 3] = v.w;
    }
    __syncthreads();
    #pragma unroll
    for (int i = 0; i < 8; i++) {
        int idx = i * 256 + threadIdx.x;
        int c = idx >> 5, rp = (idx & 31) * 2;
        __half2 hv = __floats2half2_rn(t[rp][c], t[rp + 1][c]);
        *(__half2*)(out + (size_t)(c0 + c) * R + r0 + rp) = hv;
    }
}

// V^T from f32 qkv: vt[(bh*HS + d)*T + t] = half(V[b,t,h,d])
__global__ void vt_k(const float* __restrict__ qkv, __half* __restrict__ vt)
{
    __shared__ float tile[32][33];
    int bh = blockIdx.z;
    int b = bh >> 4, h = bh & 15;
    int t0 = blockIdx.x * 32, d0 = blockIdx.y * 32;
    #pragma unroll
    for (int i = threadIdx.y; i < 32; i += 8) {
        int t = t0 + i;
        tile[i][threadIdx.x] = qkv[((size_t)(b * SEQ + t)) * (3 * DMODEL)
                                   + h * 3 * HDIM + 2 * HDIM + d0 + threadIdx.x];
    }
    __syncthreads();
    #pragma unroll
    for (int i = threadIdx.y; i < 32; i += 8) {
        int d = d0 + i;
        vt[((size_t)bh * HDIM + d) * SEQ + t0 + threadIdx.x] =
            __float2half_rn(tile[threadIdx.x][i]);
    }
}

// ---------------- elementwise kernels ----------------------------------------
__global__ void embed_k(const int* __restrict__ ids,
                        const float* __restrict__ ew, float* __restrict__ x)
{
    int idx = blockIdx.x * blockDim.x + threadIdx.x;
    if (idx >= NTOK * DMODEL) return;
    int row = idx / DMODEL, d = idx % DMODEL;
    x[idx] = ew[(long long)ids[row] * DMODEL + d];
}

// LayerNorm f32 -> half
__global__ void ln_k(const float* __restrict__ x, const float* __restrict__ s,
                     const float* __restrict__ b, __half* __restrict__ out)
{
    int row = blockIdx.x;
    const float4* xr = (const float4*)(x + (long long)row * DMODEL);
    float4 v = xr[threadIdx.x];
    float sum = v.x + v.y + v.z + v.w;
    float mean = blockReduceSum(sum) * (1.f / DMODEL);
    float dx = v.x - mean, dy = v.y - mean, dz = v.z - mean, dw = v.w - mean;
    float var = blockReduceSum(dx*dx + dy*dy + dz*dz + dw*dw) * (1.f / DMODEL);
    float r = rsqrtf(var + LN_EPS);
    float4 s4 = ((const float4*)s)[threadIdx.x];
    float4 b4 = ((const float4*)b)[threadIdx.x];
    __half2* orow = (__half2*)(out + (long long)row * DMODEL);
    orow[2*threadIdx.x]   = __floats2half2_rn(dx * r * s4.x + b4.x,
                                              dy * r * s4.y + b4.y);
    orow[2*threadIdx.x+1] = __floats2half2_rn(dz * r * s4.z + b4.z,
                                              dw * r * s4.w + b4.w);
}

// f32 qkv -> rope q,k -> half Q,K [B,H,T,HS]
__global__ void rope_split_k(const float* __restrict__ qkv,
                             __half* __restrict__ Q, __half* __restrict__ K)
{
    int idx = blockIdx.x * blockDim.x + threadIdx.x;
    if (idx >= NTOK * DMODEL) return;
    int d = idx & (HDIM - 1);
    int t = (idx >> 6) & (SEQ - 1);
    int h = (idx >> 16) & (NHEAD - 1);
    int b = idx >> 20;
    long long base = ((long long)(b * SEQ + t)) * (3 * DMODEL) + h * (3 * HDIM);
    float qv = qkv[base + d];
    float kv = qkv[base + HDIM + d];
    if (d < ROTD) {
        int fi = d & 7;
        float inv = expf(-(float)(2 * fi) / ROTD * logf(10000.0f));
        float ang = (float)t * inv;
        float c = cosf(ang), s = sinf(ang);
        int partner = (d < 8) ? d + 8 : d - 8;
        float qp = qkv[base + partner];
        float kp = qkv[base + HDIM + partner];
        float rq = (d < 8) ? -qp : qp;
        float rk = (d < 8) ? -kp : kp;
        qv = qv * c + rq * s;
        kv = kv * c + rk * s;
    }
    Q[idx] = __float2half_rn(qv); K[idx] = __float2half_rn(kv);
}

// causal softmax: f32 scores -> half probabilities.
// exp cached in smem; writes only up to the 128-aligned causal boundary.
__global__ void softmax_k(const float* __restrict__ sc, __half* __restrict__ p)
{
    __shared__ float ebuf[SEQ];
    long long r = blockIdx.x;
    int i = (int)(r & (SEQ - 1));
    const float* row = sc + r * SEQ;
    __half* prow = p + r * SEQ;
    int tid = threadIdx.x;
    float mx = -1e30f;
    for (int j = tid; j <= i; j += 256) mx = fmaxf(mx, row[j]);
    mx = blockReduceMax(mx);
    float sum = 0.f;
    for (int j = tid; j <= i; j += 256) {
        float e = expf(row[j] - mx);
        ebuf[j] = e;
        sum += e;
    }
    sum = blockReduceSum(sum);
    __syncthreads();
    float inv = 1.f / sum;
    int lim = ((i >> 7) + 1) << 7;           // causal PV reads keys < lim only
    for (int j = tid; j < lim; j += 256)
        prow[j] = (j <= i) ? __float2half_rn(ebuf[j] * inv)
                           : __float2half_rn(0.f);
}

#define S256 (2*(256*ASTR*2 + 128*ASTR*2))   // 61440
#define SPV  (2*(128*ASTR*2 + 64*ASTR*2))    // 30720

// ---------------- driver ------------------------------------------------------
extern "C" void kernel_launch(void* const* d_in, const int* in_sizes, int n_in,
                              void* d_out, int out_size)
{
    const int*   ids     = (const int*)  d_in[0];
    const float* embed_w = (const float*)d_in[1];
    const float* ln1_s   = (const float*)d_in[2];
    const float* ln1_b   = (const float*)d_in[3];
    const float* ln2_s   = (const float*)d_in[4];
    const float* ln2_b   = (const float*)d_in[5];
    const float* qkv_w   = (const float*)d_in[6];
    const float* qkv_b   = (const float*)d_in[7];
    const float* dense_w = (const float*)d_in[8];
    const float* dense_b = (const float*)d_in[9];
    const float* fc1_w   = (const float*)d_in[10];
    const float* fc1_b   = (const float*)d_in[11];
    const float* fc2_w   = (const float*)d_in[12];
    const float* fc2_b   = (const float*)d_in[13];
    const float* fln_s   = (const float*)d_in[14];
    const float* fln_b   = (const float*)d_in[15];
    const float* head_w  = (const float*)d_in[16];
    float* out = (float*)d_out;

    cudaFuncSetAttribute(gemm_h<256,128,0,0,0,0,0>, cudaFuncAttributeMaxDynamicSharedMemorySize, S256);
    cudaFuncSetAttribute(gemm_h<256,128,0,0,0,1,0>, cudaFuncAttributeMaxDynamicSharedMemorySize, S256);
    cudaFuncSetAttribute(gemm_h<256,128,1,0,1,0,0>, cudaFuncAttributeMaxDynamicSharedMemorySize, S256);
    cudaFuncSetAttribute(gemm_h<128,64,0,1,1,2,0>,  cudaFuncAttributeMaxDynamicSharedMemorySize, SPV);
    cudaFuncSetAttribute(gemm_h<128,64,0,0,0,0,0>,  cudaFuncAttributeMaxDynamicSharedMemorySize, SPV);
    cudaFuncSetAttribute(gemm_h<128,64,0,0,0,0,1>,  cudaFuncAttributeMaxDynamicSharedMemorySize, SPV);

    float *x, *qkv, *sc, *ad;
    __half *h, *Q, *K, *Vt, *p, *mg, *m1;
    __half *wq, *wd, *w1, *w2, *wh;
    cudaGetSymbolAddress((void**)&x,   g_x);
    cudaGetSymbolAddress((void**)&h,   g_h);
    cudaGetSymbolAddress((void**)&qkv, g_qkv);
    cudaGetSymbolAddress((void**)&Q,   g_q);
    cudaGetSymbolAddress((void**)&K,   g_k);
    cudaGetSymbolAddress((void**)&Vt,  g_vt);
    cudaGetSymbolAddress((void**)&sc,  g_scores);
    cudaGetSymbolAddress((void**)&p,   g_p);
    cudaGetSymbolAddress((void**)&mg,  g_mg);
    cudaGetSymbolAddress((void**)&ad,  g_attd);
    cudaGetSymbolAddress((void**)&m1,  g_m1);
    cudaGetSymbolAddress((void**)&wq,  g_wq);
    cudaGetSymbolAddress((void**)&wd,  g_wd);
    cudaGetSymbolAddress((void**)&w1,  g_w1);
    cudaGetSymbolAddress((void**)&w2,  g_w2);
    cudaGetSymbolAddress((void**)&wh,  g_wh);

    const int ELTS = NTOK * DMODEL;
    dim3 tb(32, 8);

    // ---- one-shot weight transpose + fp16 conversion ([K,N] -> [N,K]) ----
    wtr_k<<<dim3(3*DMODEL/64, DMODEL/64, LAYERS), 256>>>(qkv_w,  wq, DMODEL, 3*DMODEL);
    wtr_k<<<dim3(DMODEL/64,  DMODEL/64, LAYERS), 256>>>(dense_w, wd, DMODEL, DMODEL);
    wtr_k<<<dim3(IFF/64,     DMODEL/64, LAYERS), 256>>>(fc1_w,   w1, DMODEL, IFF);
    wtr_k<<<dim3(DMODEL/64,  IFF/64,    LAYERS), 256>>>(fc2_w,   w2, IFF, DMODEL);
    wtr_k<<<dim3(VOCAB/64,   DMODEL/64, 1),      256>>>(head_w,  wh, DMODEL, VOCAB);

    embed_k<<<(ELTS + 255) / 256, 256>>>(ids, embed_w, x);

    for (int l = 0; l < LAYERS; l++) {
        // ---- attention branch ----
        ln_k<<<NTOK, 256>>>(x, ln1_s + l * DMODEL, ln1_b + l * DMODEL, h);
        gemm_h<256,128,0,0,0,0,0><<<dim3(3 * DMODEL / 128, NTOK / 256, 1), 256, S256>>>(
            h, wq + (size_t)l * DMODEL * 3 * DMODEL,
            qkv_b + (size_t)l * 3 * DMODEL, nullptr, nullptr, qkv,
            NTOK, 3 * DMODEL, DMODEL, 0, 0, 0, 1.f);
        rope_split_k<<<(ELTS + 255) / 256, 256>>>(qkv, Q, K);
        vt_k<<<dim3(SEQ/32, HDIM/32, BATCH*NHEAD), tb>>>(qkv, Vt);
        // scores = Q K^T / sqrt(HS), causal blocks only
        gemm_h<256,128,0,0,0,1,0><<<dim3(SEQ / 128, SEQ / 256, BATCH * NHEAD), 256, S256>>>(
            Q, K, nullptr, nullptr, nullptr, sc,
            SEQ, SEQ, HDIM,
            (long long)SEQ * HDIM, (long long)SEQ * HDIM,
            (long long)SEQ * SEQ, INV_SCALE);
        softmax_k<<<BATCH * NHEAD * SEQ, 256>>>(sc, p);
        // O = P V (B = V^T [HS,T]); causal k-clamp; merged [B,T,D] half out
        gemm_h<128,64,0,1,1,2,0><<<dim3(1, SEQ / 128, BATCH * NHEAD), 128, SPV>>>(
            p, Vt, nullptr, nullptr, nullptr, mg,
            SEQ, HDIM, SEQ,
            (long long)SEQ * SEQ, (long long)HDIM * SEQ, 0, 1.f);
        // dense: 128x64 tiles -> 256 CTAs, single full wave at 2 CTA/SM
        gemm_h<128,64,0,0,0,0,0><<<dim3(DMODEL / 64, NTOK / 128, 1), 128, SPV>>>(
            mg, wd + (size_t)l * DMODEL * DMODEL,
            dense_b + (size_t)l * DMODEL, nullptr, nullptr, ad,
            NTOK, DMODEL, DMODEL, 0, 0, 0, 1.f);
        // ---- MLP branch (on original x) ----
        ln_k<<<NTOK, 256>>>(x, ln2_s + l * DMODEL, ln2_b + l * DMODEL, h);
        gemm_h<256,128,1,0,1,0,0><<<dim3(IFF / 128, NTOK / 256, 1), 256, S256>>>(
            h, w1 + (size_t)l * DMODEL * IFF,
            fc1_b + (size_t)l * IFF, nullptr, nullptr, m1,
            NTOK, IFF, DMODEL, 0, 0, 0, 1.f);
        // fc2 with fused residual: x = fc2(m1) + bias + x + ad  (128x64 tiles)
        gemm_h<128,64,0,0,0,0,1><<<dim3(DMODEL / 64, NTOK / 128, 1), 128, SPV>>>(
            m1, w2 + (size_t)l * IFF * DMODEL,
            fc2_b + (size_t)l * DMODEL, x, ad, x,
            NTOK, DMODEL, IFF, 0, 0, 0, 1.f);
    }

    // final LN + head
    ln_k<<<NTOK, 256>>>(x, fln_s, fln_b, h);
    gemm_h<256,128,0,0,0,0,0><<<dim3(VOCAB / 128, NTOK / 256, 1), 256, S256>>>(
        h, wh, nullptr, nullptr, nullptr, out,
        NTOK, VOCAB, DMODEL, 0, 0, 0, 1.f);
}